// round 2
// baseline (speedup 1.0000x reference)
#include <cuda_runtime.h>
#include <cuda_fp16.h>
#include <math.h>

#define NN   50000
#define EE   1600000
#define ETOT 1650000
#define DIN_ 128

// ------------------------- device scratch (no allocs) -------------------------
__device__ float  g_h[NN * 128];      // transformed features (fp32, for attn logits)
__device__ __half g_hh[NN * 128];     // fp16 copy for the edge gather
__device__ float  g_x[NN * 128];      // layer activations
__device__ float  g_as[NN * 8];       // per-node src attention logits
__device__ float  g_ad[NN * 8];       // per-node dst attention logits
__device__ int    g_counts[NN];
__device__ int    g_offs[NN + 1];
__device__ int    g_cursor[NN];
__device__ int    g_esrc[ETOT];
__device__ int    g_part[64];

// ------------------------- CSR build ------------------------------------------
__global__ void k_init(int* counts) {
    int i = blockIdx.x * 256 + threadIdx.x;
    if (i < NN) counts[i] = 1;  // self-loop
}

__global__ void k_hist(const int* __restrict__ A, int* counts) {
    int e = blockIdx.x * 256 + threadIdx.x;
    if (e < EE) atomicAdd(&counts[A[EE + e]], 1);
}

__global__ void k_scan1(const int* __restrict__ counts, int* offs, int* part) {
    __shared__ int sm[1024];
    int tid = threadIdx.x;
    int i = blockIdx.x * 1024 + tid;
    int v = (i < NN) ? counts[i] : 0;
    sm[tid] = v;
    __syncthreads();
    for (int off = 1; off < 1024; off <<= 1) {
        int t = (tid >= off) ? sm[tid - off] : 0;
        __syncthreads();
        sm[tid] += t;
        __syncthreads();
    }
    if (i < NN) offs[i + 1] = sm[tid];
    if (tid == 1023) part[blockIdx.x] = sm[1023];
}

__global__ void k_scan2(int* part, int nb) {
    if (threadIdx.x == 0) {
        int run = 0;
        for (int i = 0; i < nb; i++) { int t = part[i]; part[i] = run; run += t; }
    }
}

__global__ void k_scan3(int* offs, const int* __restrict__ part,
                        const int* __restrict__ counts, int* cursor) {
    int tid = threadIdx.x;
    int i = blockIdx.x * 1024 + tid;
    if (i < NN) {
        int val = offs[i + 1] + part[blockIdx.x];
        offs[i + 1] = val;
        cursor[i] = val - counts[i];
    }
    if (i == 0) offs[0] = 0;
}

__global__ void k_scatter(const int* __restrict__ A, int* cursor, int* esrc) {
    int idx = blockIdx.x * 256 + threadIdx.x;
    if (idx >= ETOT) return;
    int s, d;
    if (idx < EE) { s = A[idx]; d = A[EE + idx]; }
    else          { s = idx - EE; d = s; }
    int pos = atomicAdd(&cursor[d], 1);
    esrc[pos] = s;
}

// ------------------------- GEMM: h = x @ W  ------------------------------------
// 128xCOLS output tile per block, thread tile 8x8, THREADS = 2*COLS.
// Writes fp32 h (for attention logits) and fp16 h (for the edge gather).
template <int COLS>
__global__ __launch_bounds__(2 * COLS) void gemm_k(const float* __restrict__ X,
                                                   const float* __restrict__ W,
                                                   float* __restrict__ Hout,
                                                   __half* __restrict__ Hh) {
    constexpr int THREADS = 2 * COLS;
    constexpr int CT = COLS / 8;    // 16 or 8 column threads
    constexpr int BM = 128;
    constexpr int BK = 32;
    __shared__ float XsT[BK][BM + 4];   // transposed X tile (pad keeps float4 align)
    __shared__ float Ws[BK][COLS];

    const int t = threadIdx.x;
    const int tcol = t % CT;
    const int trow = t / CT;            // 0..15
    const int row0 = blockIdx.x * BM;

    float acc[8][8];
#pragma unroll
    for (int i = 0; i < 8; i++)
#pragma unroll
        for (int j = 0; j < 8; j++) acc[i][j] = 0.f;

#pragma unroll
    for (int kt = 0; kt < DIN_; kt += BK) {
        // W tile: rows kt..kt+31 are contiguous -> flat float4 copy
        {
            const float4* Wg = reinterpret_cast<const float4*>(W + kt * COLS);
            float4* Wsf = reinterpret_cast<float4*>(&Ws[0][0]);
#pragma unroll
            for (int i = 0; i < (8 * COLS) / THREADS; i++)
                Wsf[t + i * THREADS] = Wg[t + i * THREADS];
        }
        // X tile transposed: 128 rows x 32 k, float4 loads
        {
#pragma unroll
            for (int i = 0; i < (BM * BK / 4) / THREADS; i++) {
                int q = t + i * THREADS;
                int r = q >> 3;
                int kg = (q & 7) * 4;
                int gr = row0 + r;
                float4 v = make_float4(0.f, 0.f, 0.f, 0.f);
                if (gr < NN)
                    v = reinterpret_cast<const float4*>(X + gr * DIN_ + kt)[q & 7];
                XsT[kg + 0][r] = v.x;
                XsT[kg + 1][r] = v.y;
                XsT[kg + 2][r] = v.z;
                XsT[kg + 3][r] = v.w;
            }
        }
        __syncthreads();
#pragma unroll
        for (int k = 0; k < BK; k++) {
            float4 a0 = *reinterpret_cast<const float4*>(&XsT[k][trow * 8]);
            float4 a1 = *reinterpret_cast<const float4*>(&XsT[k][trow * 8 + 4]);
            float aa[8] = {a0.x, a0.y, a0.z, a0.w, a1.x, a1.y, a1.z, a1.w};
            float bb[8];
#pragma unroll
            for (int j = 0; j < 8; j++) bb[j] = Ws[k][tcol + j * CT];
#pragma unroll
            for (int i = 0; i < 8; i++)
#pragma unroll
                for (int j = 0; j < 8; j++) acc[i][j] += aa[i] * bb[j];
        }
        __syncthreads();
    }
#pragma unroll
    for (int i = 0; i < 8; i++) {
        int r = row0 + trow * 8 + i;
        if (r < NN) {
#pragma unroll
            for (int j = 0; j < 8; j++) {
                int c = tcol + j * CT;
                float v = acc[i][j];
                Hout[r * COLS + c] = v;
                Hh[r * COLS + c] = __float2half(v);
            }
        }
    }
}

// ------------------------- attention logits per node ---------------------------
template <int H, int F>
__global__ __launch_bounds__(256) void attn_k(const float* __restrict__ Hb,
                                              const float* __restrict__ a_s,
                                              const float* __restrict__ a_d,
                                              float* __restrict__ ASRC,
                                              float* __restrict__ ADST) {
    int n = blockIdx.x * 8 + (threadIdx.x >> 5);
    if (n >= NN) return;
    int lane = threadIdx.x & 31;
    if constexpr (H * F == 128) {
        float4 hv = reinterpret_cast<const float4*>(Hb)[n * 32 + lane];
        int head = lane >> 2;
        int f0 = (lane & 3) * 4;
        const float* a = &a_s[head * F + f0];
        const float* d = &a_d[head * F + f0];
        float ps = hv.x * a[0] + hv.y * a[1] + hv.z * a[2] + hv.w * a[3];
        float pd = hv.x * d[0] + hv.y * d[1] + hv.z * d[2] + hv.w * d[3];
        ps += __shfl_xor_sync(~0u, ps, 1); ps += __shfl_xor_sync(~0u, ps, 2);
        pd += __shfl_xor_sync(~0u, pd, 1); pd += __shfl_xor_sync(~0u, pd, 2);
        if ((lane & 3) == 0) { ASRC[n * H + head] = ps; ADST[n * H + head] = pd; }
    } else {  // H*F == 64
        float2 hv = reinterpret_cast<const float2*>(Hb)[n * 32 + lane];
        int head = lane >> 3;
        int f0 = (lane & 7) * 2;
        float ps = hv.x * a_s[head * F + f0] + hv.y * a_s[head * F + f0 + 1];
        float pd = hv.x * a_d[head * F + f0] + hv.y * a_d[head * F + f0 + 1];
        ps += __shfl_xor_sync(~0u, ps, 1); ps += __shfl_xor_sync(~0u, ps, 2);
        ps += __shfl_xor_sync(~0u, ps, 4);
        pd += __shfl_xor_sync(~0u, pd, 1); pd += __shfl_xor_sync(~0u, pd, 2);
        pd += __shfl_xor_sync(~0u, pd, 4);
        if ((lane & 7) == 0) { ASRC[n * H + head] = ps; ADST[n * H + head] = pd; }
    }
}

// ------------------------- warp-per-node online-softmax aggregation ------------
// Edge feature gather reads the fp16 table (half the L2 traffic); accumulation
// and softmax state stay fp32.
template <int H, int F, bool RELU, bool MEAN>
__global__ __launch_bounds__(256) void agg_k(const __half* __restrict__ Hh,
                                             const float* __restrict__ ASRC,
                                             const float* __restrict__ ADST,
                                             const int* __restrict__ esrc,
                                             const int* __restrict__ offs,
                                             const float* __restrict__ bias,
                                             float* __restrict__ out) {
    constexpr int HF = H * F;
    constexpr int VEC = HF / 32;
    int n = blockIdx.x * 8 + (threadIdx.x >> 5);
    if (n >= NN) return;
    int lane = threadIdx.x & 31;
    const int head = (lane * VEC) / F;

    const float adn = ADST[n * H + head];
    float m = -1e30f, s = 0.f;
    float acc[VEC];
#pragma unroll
    for (int v = 0; v < VEC; v++) acc[v] = 0.f;

    int e = offs[n];
    const int end = offs[n + 1];

    // software pipeline: 1-ahead prefetch
    int src = esrc[e];
    float ea = ASRC[src * H + head];
    float hv[VEC];
    if constexpr (VEC == 4) {
        uint2 u = reinterpret_cast<const uint2*>(Hh)[src * 32 + lane];
        float2 lo = __half22float2(*reinterpret_cast<__half2*>(&u.x));
        float2 hi = __half22float2(*reinterpret_cast<__half2*>(&u.y));
        hv[0] = lo.x; hv[1] = lo.y; hv[2] = hi.x; hv[3] = hi.y;
    } else {
        unsigned u = reinterpret_cast<const unsigned*>(Hh)[src * 32 + lane];
        float2 lo = __half22float2(*reinterpret_cast<__half2*>(&u));
        hv[0] = lo.x; hv[1] = lo.y;
    }

    while (true) {
        int e2 = e + 1;
        bool more = e2 < end;
        float ea2 = 0.f;
        float hv2[VEC];
        if (more) {
            int src2 = esrc[e2];
            ea2 = ASRC[src2 * H + head];
            if constexpr (VEC == 4) {
                uint2 u = reinterpret_cast<const uint2*>(Hh)[src2 * 32 + lane];
                float2 lo = __half22float2(*reinterpret_cast<__half2*>(&u.x));
                float2 hi = __half22float2(*reinterpret_cast<__half2*>(&u.y));
                hv2[0] = lo.x; hv2[1] = lo.y; hv2[2] = hi.x; hv2[3] = hi.y;
            } else {
                unsigned u = reinterpret_cast<const unsigned*>(Hh)[src2 * 32 + lane];
                float2 lo = __half22float2(*reinterpret_cast<__half2*>(&u));
                hv2[0] = lo.x; hv2[1] = lo.y;
            }
        }
        float ev = ea + adn;
        ev = ev > 0.f ? ev : 0.2f * ev;   // leaky relu
        float mnew = fmaxf(m, ev);
        float scale = __expf(m - mnew);
        float p = __expf(ev - mnew);
        s = fmaf(s, scale, p);
#pragma unroll
        for (int v = 0; v < VEC; v++) acc[v] = fmaf(acc[v], scale, p * hv[v]);
        m = mnew;
        if (!more) break;
        e = e2;
        ea = ea2;
#pragma unroll
        for (int v = 0; v < VEC; v++) hv[v] = hv2[v];
    }

    const float inv = 1.f / (s + 1e-16f);
    if constexpr (!MEAN) {
        float4 o;
        o.x = acc[0] * inv + bias[lane * 4 + 0];
        o.y = acc[1] * inv + bias[lane * 4 + 1];
        o.z = acc[2] * inv + bias[lane * 4 + 2];
        o.w = acc[3] * inv + bias[lane * 4 + 3];
        if (RELU) {
            o.x = fmaxf(o.x, 0.f); o.y = fmaxf(o.y, 0.f);
            o.z = fmaxf(o.z, 0.f); o.w = fmaxf(o.w, 0.f);
        }
        reinterpret_cast<float4*>(out)[n * 32 + lane] = o;
    } else {
        // VEC == 2: mean over heads, lanes l, l^8, l^16 hold same f-pair
        float ox = acc[0] * inv;
        float oy = acc[1] * inv;
        ox += __shfl_xor_sync(~0u, ox, 8);
        oy += __shfl_xor_sync(~0u, oy, 8);
        ox += __shfl_xor_sync(~0u, ox, 16);
        oy += __shfl_xor_sync(~0u, oy, 16);
        if (lane < 8) {
            out[n * 16 + 2 * lane]     = 0.25f * ox + bias[2 * lane];
            out[n * 16 + 2 * lane + 1] = 0.25f * oy + bias[2 * lane + 1];
        }
    }
}

// ------------------------- launcher -------------------------------------------
extern "C" void kernel_launch(void* const* d_in, const int* in_sizes, int n_in,
                              void* d_out, int out_size) {
    const float* X   = (const float*)d_in[0];
    const int*   A   = (const int*)d_in[1];
    const float* W1  = (const float*)d_in[2];
    const float* as1 = (const float*)d_in[3];
    const float* ad1 = (const float*)d_in[4];
    const float* b1  = (const float*)d_in[5];
    const float* W2  = (const float*)d_in[6];
    const float* as2 = (const float*)d_in[7];
    const float* ad2 = (const float*)d_in[8];
    const float* b2  = (const float*)d_in[9];
    const float* W3  = (const float*)d_in[10];
    const float* as3 = (const float*)d_in[11];
    const float* ad3 = (const float*)d_in[12];
    const float* b3  = (const float*)d_in[13];
    float* out = (float*)d_out;

    void* p;
    float *h, *x, *asb, *adb;
    __half* hh;
    int *counts, *offs, *cursor, *esrc, *part;
    cudaGetSymbolAddress(&p, g_h);      h = (float*)p;
    cudaGetSymbolAddress(&p, g_hh);     hh = (__half*)p;
    cudaGetSymbolAddress(&p, g_x);      x = (float*)p;
    cudaGetSymbolAddress(&p, g_as);     asb = (float*)p;
    cudaGetSymbolAddress(&p, g_ad);     adb = (float*)p;
    cudaGetSymbolAddress(&p, g_counts); counts = (int*)p;
    cudaGetSymbolAddress(&p, g_offs);   offs = (int*)p;
    cudaGetSymbolAddress(&p, g_cursor); cursor = (int*)p;
    cudaGetSymbolAddress(&p, g_esrc);   esrc = (int*)p;
    cudaGetSymbolAddress(&p, g_part);   part = (int*)p;

    const int NB = (NN + 1023) / 1024;  // 49

    // CSR by dst (counting sort), rebuilt every call (deterministic work)
    k_init<<<(NN + 255) / 256, 256>>>(counts);
    k_hist<<<(EE + 255) / 256, 256>>>(A, counts);
    k_scan1<<<NB, 1024>>>(counts, offs, part);
    k_scan2<<<1, 32>>>(part, NB);
    k_scan3<<<NB, 1024>>>(offs, part, counts, cursor);
    k_scatter<<<(ETOT + 255) / 256, 256>>>(A, cursor, esrc);

    const int GB = (NN + 127) / 128;  // gemm blocks (BM=128)
    const int AB = (NN + 7) / 8;      // warp-per-node blocks

    // Layer 1
    gemm_k<128><<<GB, 256>>>(X, W1, h, hh);
    attn_k<8, 16><<<AB, 256>>>(h, as1, ad1, asb, adb);
    agg_k<8, 16, true, false><<<AB, 256>>>(hh, asb, adb, esrc, offs, b1, x);
    // Layer 2
    gemm_k<128><<<GB, 256>>>(x, W2, h, hh);
    attn_k<8, 16><<<AB, 256>>>(h, as2, ad2, asb, adb);
    agg_k<8, 16, true, false><<<AB, 256>>>(hh, asb, adb, esrc, offs, b2, x);
    // Layer 3 (mean over heads)
    gemm_k<64><<<GB, 128>>>(x, W3, h, hh);
    attn_k<4, 16><<<AB, 256>>>(h, as3, ad3, asb, adb);
    agg_k<4, 16, false, true><<<AB, 256>>>(hh, asb, adb, esrc, offs, b3, out);
}

// round 3
// speedup vs baseline: 1.3128x; 1.3128x over previous
#include <cuda_runtime.h>
#include <cuda_fp16.h>
#include <math.h>

#define NN   50000
#define EE   1600000
#define ETOT 1650000
#define DIN_ 128

// ------------------------- device scratch (no allocs) -------------------------
__device__ float  g_h[NN * 128];      // transformed features (fp32, for attn logits)
__device__ __half g_hh[NN * 128];     // fp16 copy for the edge gather
__device__ float  g_x[NN * 128];      // layer activations
__device__ float  g_as[NN * 8];       // per-node src attention logits
__device__ float  g_ad[NN * 8];       // per-node dst attention logits
__device__ int    g_counts[NN];
__device__ int    g_offs[NN + 1];
__device__ int    g_cursor[NN];
__device__ int    g_esrc[ETOT];
__device__ int    g_part[64];

// ------------------------- CSR build ------------------------------------------
__global__ void k_init(int* counts) {
    int i = blockIdx.x * 256 + threadIdx.x;
    if (i < NN) counts[i] = 1;  // self-loop
}

__global__ void k_hist(const int* __restrict__ A, int* counts) {
    int e = blockIdx.x * 256 + threadIdx.x;
    if (e < EE) atomicAdd(&counts[A[EE + e]], 1);
}

__global__ void k_scan1(const int* __restrict__ counts, int* offs, int* part) {
    __shared__ int sm[1024];
    int tid = threadIdx.x;
    int i = blockIdx.x * 1024 + tid;
    int v = (i < NN) ? counts[i] : 0;
    sm[tid] = v;
    __syncthreads();
    for (int off = 1; off < 1024; off <<= 1) {
        int t = (tid >= off) ? sm[tid - off] : 0;
        __syncthreads();
        sm[tid] += t;
        __syncthreads();
    }
    if (i < NN) offs[i + 1] = sm[tid];
    if (tid == 1023) part[blockIdx.x] = sm[1023];
}

__global__ void k_scan2(int* part, int nb) {
    if (threadIdx.x == 0) {
        int run = 0;
        for (int i = 0; i < nb; i++) { int t = part[i]; part[i] = run; run += t; }
    }
}

__global__ void k_scan3(int* offs, const int* __restrict__ part,
                        const int* __restrict__ counts, int* cursor) {
    int tid = threadIdx.x;
    int i = blockIdx.x * 1024 + tid;
    if (i < NN) {
        int val = offs[i + 1] + part[blockIdx.x];
        offs[i + 1] = val;
        cursor[i] = val - counts[i];
    }
    if (i == 0) offs[0] = 0;
}

__global__ void k_scatter(const int* __restrict__ A, int* cursor, int* esrc) {
    int idx = blockIdx.x * 256 + threadIdx.x;
    if (idx >= ETOT) return;
    int s, d;
    if (idx < EE) { s = A[idx]; d = A[EE + idx]; }
    else          { s = idx - EE; d = s; }
    int pos = atomicAdd(&cursor[d], 1);
    esrc[pos] = s;
}

// ------------------------- GEMM: h = x @ W  ------------------------------------
// R1 tiling: BM=64 rows/block, full COLS width, thread tile 8x8, THREADS == COLS.
// kt loop NOT unrolled (code-size discipline); inner k unrolled by 8 only.
// Epilogue writes fp32 h (attn logits) and fp16 h (edge gather).
template <int COLS>
__global__ __launch_bounds__(COLS) void gemm_k(const float* __restrict__ X,
                                               const float* __restrict__ W,
                                               float* __restrict__ Hout,
                                               __half* __restrict__ Hh) {
    constexpr int CT = COLS / 8;  // column threads
    constexpr int KT = 32;
    __shared__ float XsT[KT][68];     // transposed X tile, padded
    __shared__ float Ws[KT][COLS];

    const int t = threadIdx.x;
    const int tcol = t % CT;
    const int trow = t / CT;
    const int row0 = blockIdx.x * 64;

    float acc[8][8];
#pragma unroll
    for (int i = 0; i < 8; i++)
#pragma unroll
        for (int j = 0; j < 8; j++) acc[i][j] = 0.f;

    for (int kt = 0; kt < DIN_; kt += KT) {
        // load W tile: Ws[i][t] (coalesced)
#pragma unroll
        for (int i = 0; i < KT; i++) Ws[i][t] = W[(kt + i) * COLS + t];
        // load X tile transposed: 64 rows x 32 k
        {
            const int k = t & 31;
            const int rb = t >> 5;
            constexpr int STEP = COLS / 32;
#pragma unroll
            for (int r = rb; r < 64; r += STEP) {
                int gr = row0 + r;
                XsT[k][r] = (gr < NN) ? X[gr * DIN_ + kt + k] : 0.f;
            }
        }
        __syncthreads();
#pragma unroll 8
        for (int k = 0; k < KT; k++) {
            float4 a0 = *reinterpret_cast<const float4*>(&XsT[k][trow * 8]);
            float4 a1 = *reinterpret_cast<const float4*>(&XsT[k][trow * 8 + 4]);
            float aa[8] = {a0.x, a0.y, a0.z, a0.w, a1.x, a1.y, a1.z, a1.w};
            float bb[8];
#pragma unroll
            for (int j = 0; j < 8; j++) bb[j] = Ws[k][tcol + j * CT];
#pragma unroll
            for (int i = 0; i < 8; i++)
#pragma unroll
                for (int j = 0; j < 8; j++) acc[i][j] += aa[i] * bb[j];
        }
        __syncthreads();
    }
#pragma unroll
    for (int i = 0; i < 8; i++) {
        int r = row0 + trow * 8 + i;
        if (r < NN) {
#pragma unroll
            for (int j = 0; j < 8; j++) {
                int c = tcol + j * CT;
                float v = acc[i][j];
                Hout[r * COLS + c] = v;
                Hh[r * COLS + c] = __float2half(v);
            }
        }
    }
}

// ------------------------- attention logits per node ---------------------------
template <int H, int F>
__global__ __launch_bounds__(256) void attn_k(const float* __restrict__ Hb,
                                              const float* __restrict__ a_s,
                                              const float* __restrict__ a_d,
                                              float* __restrict__ ASRC,
                                              float* __restrict__ ADST) {
    int n = blockIdx.x * 8 + (threadIdx.x >> 5);
    if (n >= NN) return;
    int lane = threadIdx.x & 31;
    if constexpr (H * F == 128) {
        float4 hv = reinterpret_cast<const float4*>(Hb)[n * 32 + lane];
        int head = lane >> 2;
        int f0 = (lane & 3) * 4;
        const float* a = &a_s[head * F + f0];
        const float* d = &a_d[head * F + f0];
        float ps = hv.x * a[0] + hv.y * a[1] + hv.z * a[2] + hv.w * a[3];
        float pd = hv.x * d[0] + hv.y * d[1] + hv.z * d[2] + hv.w * d[3];
        ps += __shfl_xor_sync(~0u, ps, 1); ps += __shfl_xor_sync(~0u, ps, 2);
        pd += __shfl_xor_sync(~0u, pd, 1); pd += __shfl_xor_sync(~0u, pd, 2);
        if ((lane & 3) == 0) { ASRC[n * H + head] = ps; ADST[n * H + head] = pd; }
    } else {  // H*F == 64
        float2 hv = reinterpret_cast<const float2*>(Hb)[n * 32 + lane];
        int head = lane >> 3;
        int f0 = (lane & 7) * 2;
        float ps = hv.x * a_s[head * F + f0] + hv.y * a_s[head * F + f0 + 1];
        float pd = hv.x * a_d[head * F + f0] + hv.y * a_d[head * F + f0 + 1];
        ps += __shfl_xor_sync(~0u, ps, 1); ps += __shfl_xor_sync(~0u, ps, 2);
        ps += __shfl_xor_sync(~0u, ps, 4);
        pd += __shfl_xor_sync(~0u, pd, 1); pd += __shfl_xor_sync(~0u, pd, 2);
        pd += __shfl_xor_sync(~0u, pd, 4);
        if ((lane & 7) == 0) { ASRC[n * H + head] = ps; ADST[n * H + head] = pd; }
    }
}

// ------------------------- warp-per-node online-softmax aggregation ------------
// Edge feature gather reads the fp16 table (half the L2 traffic); accumulation
// and softmax state stay fp32.
template <int H, int F, bool RELU, bool MEAN>
__global__ __launch_bounds__(256) void agg_k(const __half* __restrict__ Hh,
                                             const float* __restrict__ ASRC,
                                             const float* __restrict__ ADST,
                                             const int* __restrict__ esrc,
                                             const int* __restrict__ offs,
                                             const float* __restrict__ bias,
                                             float* __restrict__ out) {
    constexpr int HF = H * F;
    constexpr int VEC = HF / 32;
    int n = blockIdx.x * 8 + (threadIdx.x >> 5);
    if (n >= NN) return;
    int lane = threadIdx.x & 31;
    const int head = (lane * VEC) / F;

    const float adn = ADST[n * H + head];
    float m = -1e30f, s = 0.f;
    float acc[VEC];
#pragma unroll
    for (int v = 0; v < VEC; v++) acc[v] = 0.f;

    int e = offs[n];
    const int end = offs[n + 1];

    // software pipeline: 1-ahead prefetch
    int src = esrc[e];
    float ea = ASRC[src * H + head];
    float hv[VEC];
    if constexpr (VEC == 4) {
        uint2 u = reinterpret_cast<const uint2*>(Hh)[src * 32 + lane];
        float2 lo = __half22float2(*reinterpret_cast<__half2*>(&u.x));
        float2 hi = __half22float2(*reinterpret_cast<__half2*>(&u.y));
        hv[0] = lo.x; hv[1] = lo.y; hv[2] = hi.x; hv[3] = hi.y;
    } else {
        unsigned u = reinterpret_cast<const unsigned*>(Hh)[src * 32 + lane];
        float2 lo = __half22float2(*reinterpret_cast<__half2*>(&u));
        hv[0] = lo.x; hv[1] = lo.y;
    }

    while (true) {
        int e2 = e + 1;
        bool more = e2 < end;
        float ea2 = 0.f;
        float hv2[VEC];
        if (more) {
            int src2 = esrc[e2];
            ea2 = ASRC[src2 * H + head];
            if constexpr (VEC == 4) {
                uint2 u = reinterpret_cast<const uint2*>(Hh)[src2 * 32 + lane];
                float2 lo = __half22float2(*reinterpret_cast<__half2*>(&u.x));
                float2 hi = __half22float2(*reinterpret_cast<__half2*>(&u.y));
                hv2[0] = lo.x; hv2[1] = lo.y; hv2[2] = hi.x; hv2[3] = hi.y;
            } else {
                unsigned u = reinterpret_cast<const unsigned*>(Hh)[src2 * 32 + lane];
                float2 lo = __half22float2(*reinterpret_cast<__half2*>(&u));
                hv2[0] = lo.x; hv2[1] = lo.y;
            }
        }
        float ev = ea + adn;
        ev = ev > 0.f ? ev : 0.2f * ev;   // leaky relu
        float mnew = fmaxf(m, ev);
        float scale = __expf(m - mnew);
        float p = __expf(ev - mnew);
        s = fmaf(s, scale, p);
#pragma unroll
        for (int v = 0; v < VEC; v++) acc[v] = fmaf(acc[v], scale, p * hv[v]);
        m = mnew;
        if (!more) break;
        e = e2;
        ea = ea2;
#pragma unroll
        for (int v = 0; v < VEC; v++) hv[v] = hv2[v];
    }

    const float inv = 1.f / (s + 1e-16f);
    if constexpr (!MEAN) {
        float4 o;
        o.x = acc[0] * inv + bias[lane * 4 + 0];
        o.y = acc[1] * inv + bias[lane * 4 + 1];
        o.z = acc[2] * inv + bias[lane * 4 + 2];
        o.w = acc[3] * inv + bias[lane * 4 + 3];
        if (RELU) {
            o.x = fmaxf(o.x, 0.f); o.y = fmaxf(o.y, 0.f);
            o.z = fmaxf(o.z, 0.f); o.w = fmaxf(o.w, 0.f);
        }
        reinterpret_cast<float4*>(out)[n * 32 + lane] = o;
    } else {
        // VEC == 2: mean over heads, lanes l, l^8, l^16 hold same f-pair
        float ox = acc[0] * inv;
        float oy = acc[1] * inv;
        ox += __shfl_xor_sync(~0u, ox, 8);
        oy += __shfl_xor_sync(~0u, oy, 8);
        ox += __shfl_xor_sync(~0u, ox, 16);
        oy += __shfl_xor_sync(~0u, oy, 16);
        if (lane < 8) {
            out[n * 16 + 2 * lane]     = 0.25f * ox + bias[2 * lane];
            out[n * 16 + 2 * lane + 1] = 0.25f * oy + bias[2 * lane + 1];
        }
    }
}

// ------------------------- launcher -------------------------------------------
extern "C" void kernel_launch(void* const* d_in, const int* in_sizes, int n_in,
                              void* d_out, int out_size) {
    const float* X   = (const float*)d_in[0];
    const int*   A   = (const int*)d_in[1];
    const float* W1  = (const float*)d_in[2];
    const float* as1 = (const float*)d_in[3];
    const float* ad1 = (const float*)d_in[4];
    const float* b1  = (const float*)d_in[5];
    const float* W2  = (const float*)d_in[6];
    const float* as2 = (const float*)d_in[7];
    const float* ad2 = (const float*)d_in[8];
    const float* b2  = (const float*)d_in[9];
    const float* W3  = (const float*)d_in[10];
    const float* as3 = (const float*)d_in[11];
    const float* ad3 = (const float*)d_in[12];
    const float* b3  = (const float*)d_in[13];
    float* out = (float*)d_out;

    void* p;
    float *h, *x, *asb, *adb;
    __half* hh;
    int *counts, *offs, *cursor, *esrc, *part;
    cudaGetSymbolAddress(&p, g_h);      h = (float*)p;
    cudaGetSymbolAddress(&p, g_hh);     hh = (__half*)p;
    cudaGetSymbolAddress(&p, g_x);      x = (float*)p;
    cudaGetSymbolAddress(&p, g_as);     asb = (float*)p;
    cudaGetSymbolAddress(&p, g_ad);     adb = (float*)p;
    cudaGetSymbolAddress(&p, g_counts); counts = (int*)p;
    cudaGetSymbolAddress(&p, g_offs);   offs = (int*)p;
    cudaGetSymbolAddress(&p, g_cursor); cursor = (int*)p;
    cudaGetSymbolAddress(&p, g_esrc);   esrc = (int*)p;
    cudaGetSymbolAddress(&p, g_part);   part = (int*)p;

    const int NB = (NN + 1023) / 1024;  // 49

    // CSR by dst (counting sort), rebuilt every call (deterministic work)
    k_init<<<(NN + 255) / 256, 256>>>(counts);
    k_hist<<<(EE + 255) / 256, 256>>>(A, counts);
    k_scan1<<<NB, 1024>>>(counts, offs, part);
    k_scan2<<<1, 32>>>(part, NB);
    k_scan3<<<NB, 1024>>>(offs, part, counts, cursor);
    k_scatter<<<(ETOT + 255) / 256, 256>>>(A, cursor, esrc);

    const int GB = (NN + 63) / 64;   // gemm blocks (BM=64)
    const int AB = (NN + 7) / 8;     // warp-per-node blocks

    // Layer 1
    gemm_k<128><<<GB, 128>>>(X, W1, h, hh);
    attn_k<8, 16><<<AB, 256>>>(h, as1, ad1, asb, adb);
    agg_k<8, 16, true, false><<<AB, 256>>>(hh, asb, adb, esrc, offs, b1, x);
    // Layer 2
    gemm_k<128><<<GB, 128>>>(x, W2, h, hh);
    attn_k<8, 16><<<AB, 256>>>(h, as2, ad2, asb, adb);
    agg_k<8, 16, true, false><<<AB, 256>>>(hh, asb, adb, esrc, offs, b2, x);
    // Layer 3 (mean over heads)
    gemm_k<64><<<GB, 64>>>(x, W3, h, hh);
    attn_k<4, 16><<<AB, 256>>>(h, as3, ad3, asb, adb);
    agg_k<4, 16, false, true><<<AB, 256>>>(hh, asb, adb, esrc, offs, b3, out);
}

// round 4
// speedup vs baseline: 1.5559x; 1.1852x over previous
#include <cuda_runtime.h>
#include <cuda_fp16.h>
#include <math.h>

#define NN   50000
#define EE   1600000
#define ETOT 1650000
#define DIN_ 128

// ------------------------- device scratch (no allocs) -------------------------
__device__ float  g_h[NN * 128];      // transformed features (fp32, for attn logits)
__device__ __half g_hh[NN * 128];     // fp16 copy for the edge gather
__device__ float  g_x[NN * 128];      // layer activations
__device__ float  g_as[NN * 8];       // per-node src attention logits
__device__ float  g_ad[NN * 8];       // per-node dst attention logits
__device__ int    g_counts[NN];
__device__ int    g_offs[NN + 1];
__device__ int    g_cursor[NN];
__device__ int    g_esrc[ETOT];
__device__ int    g_part[64];

// ------------------------- CSR build ------------------------------------------
__global__ void k_init(int* counts) {
    int i = blockIdx.x * 256 + threadIdx.x;
    if (i < NN) counts[i] = 1;  // self-loop
}

__global__ void k_hist(const int* __restrict__ A, int* counts) {
    int e = blockIdx.x * 256 + threadIdx.x;
    if (e < EE) atomicAdd(&counts[A[EE + e]], 1);
}

__global__ void k_scan1(const int* __restrict__ counts, int* offs, int* part) {
    __shared__ int sm[1024];
    int tid = threadIdx.x;
    int i = blockIdx.x * 1024 + tid;
    int v = (i < NN) ? counts[i] : 0;
    sm[tid] = v;
    __syncthreads();
    for (int off = 1; off < 1024; off <<= 1) {
        int t = (tid >= off) ? sm[tid - off] : 0;
        __syncthreads();
        sm[tid] += t;
        __syncthreads();
    }
    if (i < NN) offs[i + 1] = sm[tid];
    if (tid == 1023) part[blockIdx.x] = sm[1023];
}

__global__ void k_scan2(int* part, int nb) {
    if (threadIdx.x == 0) {
        int run = 0;
        for (int i = 0; i < nb; i++) { int t = part[i]; part[i] = run; run += t; }
    }
}

__global__ void k_scan3(int* offs, const int* __restrict__ part,
                        const int* __restrict__ counts, int* cursor) {
    int tid = threadIdx.x;
    int i = blockIdx.x * 1024 + tid;
    if (i < NN) {
        int val = offs[i + 1] + part[blockIdx.x];
        offs[i + 1] = val;
        cursor[i] = val - counts[i];
    }
    if (i == 0) offs[0] = 0;
}

__global__ void k_scatter(const int* __restrict__ A, int* cursor, int* esrc) {
    int idx = blockIdx.x * 256 + threadIdx.x;
    if (idx >= ETOT) return;
    int s, d;
    if (idx < EE) { s = A[idx]; d = A[EE + idx]; }
    else          { s = idx - EE; d = s; }
    int pos = atomicAdd(&cursor[d], 1);
    esrc[pos] = s;
}

// ------------------------- tensor-core GEMM: h = x @ W (tf32 mma) --------------
__device__ __forceinline__ unsigned f2tf32(float f) {
    unsigned u;
    asm("cvt.rna.tf32.f32 %0, %1;" : "=r"(u) : "f"(f));
    return u;
}

// BM=128 rows/block, 256 threads (8 warps), BK=32, K=128 fixed.
// COLS=128: warps 4(M)x2(N), warp tile 32x64. COLS=64: warps 8(M)x1, tile 16x64.
template <int COLS>
__global__ __launch_bounds__(256) void gemm_tc(const float* __restrict__ X,
                                               const float* __restrict__ W,
                                               float* __restrict__ Hout,
                                               __half* __restrict__ Hh) {
    constexpr int BM = 128, BK = 32;
    constexpr int WM = (COLS == 128) ? 4 : 8;   // warps along M
    constexpr int MF = BM / (WM * 16);          // m16 frags per warp (2 or 1)
    constexpr int NF = 8;                       // n8 frags per warp (covers 64 cols)
    constexpr int APAD = BK + 4;                // 36: banks (4*(t/4)+t%4) distinct
    constexpr int WPAD = COLS + 8;              // banks (8*(t%4)+t/4) distinct

    __shared__ float As[BM][APAD];
    __shared__ float Ws[BK][WPAD];

    const int t = threadIdx.x;
    const int lane = t & 31;
    const int wid = t >> 5;
    const int wm = wid % WM;
    const int wn = wid / WM;          // 0..1 (COLS=128) or 0 (COLS=64)
    const int row0 = blockIdx.x * BM;
    const int g = lane >> 2;          // 0..7
    const int q4 = lane & 3;          // 0..3

    float acc[MF][NF][4];
#pragma unroll
    for (int mf = 0; mf < MF; mf++)
#pragma unroll
        for (int nf = 0; nf < NF; nf++)
#pragma unroll
            for (int i = 0; i < 4; i++) acc[mf][nf][i] = 0.f;

#pragma unroll 1
    for (int kt = 0; kt < DIN_; kt += BK) {
        // W tile: BK x COLS, contiguous rows -> float4 copy with tf32 cvt
        {
            constexpr int NV = BK * COLS / 4 / 256;  // 4 or 2
            const float4* Wg = reinterpret_cast<const float4*>(W + kt * COLS);
#pragma unroll
            for (int i = 0; i < NV; i++) {
                int qq = t + i * 256;
                int r = qq / (COLS / 4), c = qq % (COLS / 4);
                float4 v = Wg[qq];
                uint4 u = make_uint4(f2tf32(v.x), f2tf32(v.y), f2tf32(v.z), f2tf32(v.w));
                *reinterpret_cast<uint4*>(&Ws[r][c * 4]) = u;
            }
        }
        // X tile: BM x BK rows -> float4 copy with tf32 cvt
        {
#pragma unroll
            for (int i = 0; i < 4; i++) {          // BM*BK/4/256 = 4
                int qq = t + i * 256;
                int r = qq >> 3, c = qq & 7;
                int gr = row0 + r;
                float4 v = make_float4(0.f, 0.f, 0.f, 0.f);
                if (gr < NN)
                    v = reinterpret_cast<const float4*>(X + gr * DIN_ + kt)[c];
                uint4 u = make_uint4(f2tf32(v.x), f2tf32(v.y), f2tf32(v.z), f2tf32(v.w));
                *reinterpret_cast<uint4*>(&As[r][c * 4]) = u;
            }
        }
        __syncthreads();
#pragma unroll
        for (int k8 = 0; k8 < BK; k8 += 8) {
            unsigned a[MF][4];
#pragma unroll
            for (int mf = 0; mf < MF; mf++) {
                int r = wm * (MF * 16) + mf * 16 + g;
                a[mf][0] = __float_as_uint(As[r][k8 + q4]);
                a[mf][1] = __float_as_uint(As[r + 8][k8 + q4]);
                a[mf][2] = __float_as_uint(As[r][k8 + q4 + 4]);
                a[mf][3] = __float_as_uint(As[r + 8][k8 + q4 + 4]);
            }
            unsigned b[NF][2];
#pragma unroll
            for (int nf = 0; nf < NF; nf++) {
                int c = wn * 64 + nf * 8 + g;
                b[nf][0] = __float_as_uint(Ws[k8 + q4][c]);
                b[nf][1] = __float_as_uint(Ws[k8 + q4 + 4][c]);
            }
#pragma unroll
            for (int mf = 0; mf < MF; mf++)
#pragma unroll
                for (int nf = 0; nf < NF; nf++)
                    asm volatile(
                        "mma.sync.aligned.m16n8k8.row.col.f32.tf32.tf32.f32 "
                        "{%0,%1,%2,%3}, {%4,%5,%6,%7}, {%8,%9}, {%0,%1,%2,%3};"
                        : "+f"(acc[mf][nf][0]), "+f"(acc[mf][nf][1]),
                          "+f"(acc[mf][nf][2]), "+f"(acc[mf][nf][3])
                        : "r"(a[mf][0]), "r"(a[mf][1]), "r"(a[mf][2]), "r"(a[mf][3]),
                          "r"(b[nf][0]), "r"(b[nf][1]));
        }
        __syncthreads();
    }

    // epilogue: c0,c1 at (row, col..col+1), c2,c3 at (row+8)
#pragma unroll
    for (int mf = 0; mf < MF; mf++) {
        int r = row0 + wm * (MF * 16) + mf * 16 + g;
#pragma unroll
        for (int nf = 0; nf < NF; nf++) {
            int c = wn * 64 + nf * 8 + 2 * q4;
            if (r < NN) {
                float2 v = make_float2(acc[mf][nf][0], acc[mf][nf][1]);
                *reinterpret_cast<float2*>(&Hout[r * COLS + c]) = v;
                *reinterpret_cast<__half2*>(&Hh[r * COLS + c]) = __floats2half2_rn(v.x, v.y);
            }
            if (r + 8 < NN) {
                float2 v = make_float2(acc[mf][nf][2], acc[mf][nf][3]);
                *reinterpret_cast<float2*>(&Hout[(r + 8) * COLS + c]) = v;
                *reinterpret_cast<__half2*>(&Hh[(r + 8) * COLS + c]) = __floats2half2_rn(v.x, v.y);
            }
        }
    }
}

// ------------------------- attention logits per node ---------------------------
template <int H, int F>
__global__ __launch_bounds__(256) void attn_k(const float* __restrict__ Hb,
                                              const float* __restrict__ a_s,
                                              const float* __restrict__ a_d,
                                              float* __restrict__ ASRC,
                                              float* __restrict__ ADST) {
    int n = blockIdx.x * 8 + (threadIdx.x >> 5);
    if (n >= NN) return;
    int lane = threadIdx.x & 31;
    if constexpr (H * F == 128) {
        float4 hv = reinterpret_cast<const float4*>(Hb)[n * 32 + lane];
        int head = lane >> 2;
        int f0 = (lane & 3) * 4;
        const float* a = &a_s[head * F + f0];
        const float* d = &a_d[head * F + f0];
        float ps = hv.x * a[0] + hv.y * a[1] + hv.z * a[2] + hv.w * a[3];
        float pd = hv.x * d[0] + hv.y * d[1] + hv.z * d[2] + hv.w * d[3];
        ps += __shfl_xor_sync(~0u, ps, 1); ps += __shfl_xor_sync(~0u, ps, 2);
        pd += __shfl_xor_sync(~0u, pd, 1); pd += __shfl_xor_sync(~0u, pd, 2);
        if ((lane & 3) == 0) { ASRC[n * H + head] = ps; ADST[n * H + head] = pd; }
    } else {  // H*F == 64
        float2 hv = reinterpret_cast<const float2*>(Hb)[n * 32 + lane];
        int head = lane >> 3;
        int f0 = (lane & 7) * 2;
        float ps = hv.x * a_s[head * F + f0] + hv.y * a_s[head * F + f0 + 1];
        float pd = hv.x * a_d[head * F + f0] + hv.y * a_d[head * F + f0 + 1];
        ps += __shfl_xor_sync(~0u, ps, 1); ps += __shfl_xor_sync(~0u, ps, 2);
        ps += __shfl_xor_sync(~0u, ps, 4);
        pd += __shfl_xor_sync(~0u, pd, 1); pd += __shfl_xor_sync(~0u, pd, 2);
        pd += __shfl_xor_sync(~0u, pd, 4);
        if ((lane & 7) == 0) { ASRC[n * H + head] = ps; ADST[n * H + head] = pd; }
    }
}

// ------------------------- warp-per-node online-softmax aggregation ------------
template <int H, int F, bool RELU, bool MEAN>
__global__ __launch_bounds__(256) void agg_k(const __half* __restrict__ Hh,
                                             const float* __restrict__ ASRC,
                                             const float* __restrict__ ADST,
                                             const int* __restrict__ esrc,
                                             const int* __restrict__ offs,
                                             const float* __restrict__ bias,
                                             float* __restrict__ out) {
    constexpr int HF = H * F;
    constexpr int VEC = HF / 32;
    int n = blockIdx.x * 8 + (threadIdx.x >> 5);
    if (n >= NN) return;
    int lane = threadIdx.x & 31;
    const int head = (lane * VEC) / F;

    const float adn = ADST[n * H + head];
    float m = -1e30f, s = 0.f;
    float acc[VEC];
#pragma unroll
    for (int v = 0; v < VEC; v++) acc[v] = 0.f;

    int e = offs[n];
    const int end = offs[n + 1];

    int src = esrc[e];
    float ea = ASRC[src * H + head];
    float hv[VEC];
    if constexpr (VEC == 4) {
        uint2 u = reinterpret_cast<const uint2*>(Hh)[src * 32 + lane];
        float2 lo = __half22float2(*reinterpret_cast<__half2*>(&u.x));
        float2 hi = __half22float2(*reinterpret_cast<__half2*>(&u.y));
        hv[0] = lo.x; hv[1] = lo.y; hv[2] = hi.x; hv[3] = hi.y;
    } else {
        unsigned u = reinterpret_cast<const unsigned*>(Hh)[src * 32 + lane];
        float2 lo = __half22float2(*reinterpret_cast<__half2*>(&u));
        hv[0] = lo.x; hv[1] = lo.y;
    }

    while (true) {
        int e2 = e + 1;
        bool more = e2 < end;
        float ea2 = 0.f;
        float hv2[VEC];
        if (more) {
            int src2 = esrc[e2];
            ea2 = ASRC[src2 * H + head];
            if constexpr (VEC == 4) {
                uint2 u = reinterpret_cast<const uint2*>(Hh)[src2 * 32 + lane];
                float2 lo = __half22float2(*reinterpret_cast<__half2*>(&u.x));
                float2 hi = __half22float2(*reinterpret_cast<__half2*>(&u.y));
                hv2[0] = lo.x; hv2[1] = lo.y; hv2[2] = hi.x; hv2[3] = hi.y;
            } else {
                unsigned u = reinterpret_cast<const unsigned*>(Hh)[src2 * 32 + lane];
                float2 lo = __half22float2(*reinterpret_cast<__half2*>(&u));
                hv2[0] = lo.x; hv2[1] = lo.y;
            }
        }
        float ev = ea + adn;
        ev = ev > 0.f ? ev : 0.2f * ev;   // leaky relu
        float mnew = fmaxf(m, ev);
        float scale = __expf(m - mnew);
        float p = __expf(ev - mnew);
        s = fmaf(s, scale, p);
#pragma unroll
        for (int v = 0; v < VEC; v++) acc[v] = fmaf(acc[v], scale, p * hv[v]);
        m = mnew;
        if (!more) break;
        e = e2;
        ea = ea2;
#pragma unroll
        for (int v = 0; v < VEC; v++) hv[v] = hv2[v];
    }

    const float inv = 1.f / (s + 1e-16f);
    if constexpr (!MEAN) {
        float4 o;
        o.x = acc[0] * inv + bias[lane * 4 + 0];
        o.y = acc[1] * inv + bias[lane * 4 + 1];
        o.z = acc[2] * inv + bias[lane * 4 + 2];
        o.w = acc[3] * inv + bias[lane * 4 + 3];
        if (RELU) {
            o.x = fmaxf(o.x, 0.f); o.y = fmaxf(o.y, 0.f);
            o.z = fmaxf(o.z, 0.f); o.w = fmaxf(o.w, 0.f);
        }
        reinterpret_cast<float4*>(out)[n * 32 + lane] = o;
    } else {
        float ox = acc[0] * inv;
        float oy = acc[1] * inv;
        ox += __shfl_xor_sync(~0u, ox, 8);
        oy += __shfl_xor_sync(~0u, oy, 8);
        ox += __shfl_xor_sync(~0u, ox, 16);
        oy += __shfl_xor_sync(~0u, oy, 16);
        if (lane < 8) {
            out[n * 16 + 2 * lane]     = 0.25f * ox + bias[2 * lane];
            out[n * 16 + 2 * lane + 1] = 0.25f * oy + bias[2 * lane + 1];
        }
    }
}

// ------------------------- launcher -------------------------------------------
extern "C" void kernel_launch(void* const* d_in, const int* in_sizes, int n_in,
                              void* d_out, int out_size) {
    const float* X   = (const float*)d_in[0];
    const int*   A   = (const int*)d_in[1];
    const float* W1  = (const float*)d_in[2];
    const float* as1 = (const float*)d_in[3];
    const float* ad1 = (const float*)d_in[4];
    const float* b1  = (const float*)d_in[5];
    const float* W2  = (const float*)d_in[6];
    const float* as2 = (const float*)d_in[7];
    const float* ad2 = (const float*)d_in[8];
    const float* b2  = (const float*)d_in[9];
    const float* W3  = (const float*)d_in[10];
    const float* as3 = (const float*)d_in[11];
    const float* ad3 = (const float*)d_in[12];
    const float* b3  = (const float*)d_in[13];
    float* out = (float*)d_out;

    void* p;
    float *h, *x, *asb, *adb;
    __half* hh;
    int *counts, *offs, *cursor, *esrc, *part;
    cudaGetSymbolAddress(&p, g_h);      h = (float*)p;
    cudaGetSymbolAddress(&p, g_hh);     hh = (__half*)p;
    cudaGetSymbolAddress(&p, g_x);      x = (float*)p;
    cudaGetSymbolAddress(&p, g_as);     asb = (float*)p;
    cudaGetSymbolAddress(&p, g_ad);     adb = (float*)p;
    cudaGetSymbolAddress(&p, g_counts); counts = (int*)p;
    cudaGetSymbolAddress(&p, g_offs);   offs = (int*)p;
    cudaGetSymbolAddress(&p, g_cursor); cursor = (int*)p;
    cudaGetSymbolAddress(&p, g_esrc);   esrc = (int*)p;
    cudaGetSymbolAddress(&p, g_part);   part = (int*)p;

    const int NB = (NN + 1023) / 1024;  // 49

    // CSR by dst (counting sort), rebuilt every call (deterministic work)
    k_init<<<(NN + 255) / 256, 256>>>(counts);
    k_hist<<<(EE + 255) / 256, 256>>>(A, counts);
    k_scan1<<<NB, 1024>>>(counts, offs, part);
    k_scan2<<<1, 32>>>(part, NB);
    k_scan3<<<NB, 1024>>>(offs, part, counts, cursor);
    k_scatter<<<(ETOT + 255) / 256, 256>>>(A, cursor, esrc);

    const int GB = (NN + 127) / 128;  // 391 blocks
    const int AB = (NN + 7) / 8;      // warp-per-node blocks

    // Layer 1
    gemm_tc<128><<<GB, 256>>>(X, W1, h, hh);
    attn_k<8, 16><<<AB, 256>>>(h, as1, ad1, asb, adb);
    agg_k<8, 16, true, false><<<AB, 256>>>(hh, asb, adb, esrc, offs, b1, x);
    // Layer 2
    gemm_tc<128><<<GB, 256>>>(x, W2, h, hh);
    attn_k<8, 16><<<AB, 256>>>(h, as2, ad2, asb, adb);
    agg_k<8, 16, true, false><<<AB, 256>>>(hh, asb, adb, esrc, offs, b2, x);
    // Layer 3 (mean over heads)
    gemm_tc<64><<<GB, 256>>>(x, W3, h, hh);
    attn_k<4, 16><<<AB, 256>>>(h, as3, ad3, asb, adb);
    agg_k<4, 16, false, true><<<AB, 256>>>(hh, asb, adb, esrc, offs, b3, out);
}

// round 5
// speedup vs baseline: 2.1397x; 1.3752x over previous
#include <cuda_runtime.h>
#include <cuda_fp16.h>
#include <math.h>

#define NN   50000
#define EE   1600000
#define ETOT 1650000
#define DIN_ 128

// ------------------------- device scratch (no allocs) -------------------------
__device__ float  g_h[NN * 128];      // transformed features (fp32, for attn logits)
__device__ __half g_hh[NN * 128];     // fp16 copy for the edge gather
__device__ float  g_x[NN * 128];      // layer activations
__device__ float  g_as[NN * 8];       // per-node src attention logits
__device__ float  g_ad[NN * 8];       // per-node dst attention logits
__device__ int    g_counts[NN];
__device__ int    g_offs[NN + 1];
__device__ int    g_cursor[NN];
__device__ int    g_esrc[ETOT];
__device__ int    g_part[64];

// ------------------------- CSR build ------------------------------------------
__global__ void k_init(int* counts) {
    int i = blockIdx.x * 256 + threadIdx.x;
    if (i < NN) counts[i] = 1;  // self-loop
}

__global__ void k_hist(const int* __restrict__ A, int* counts) {
    int e = blockIdx.x * 256 + threadIdx.x;
    if (e < EE) atomicAdd(&counts[A[EE + e]], 1);
}

__global__ void k_scan1(const int* __restrict__ counts, int* offs, int* part) {
    __shared__ int sm[1024];
    int tid = threadIdx.x;
    int i = blockIdx.x * 1024 + tid;
    int v = (i < NN) ? counts[i] : 0;
    sm[tid] = v;
    __syncthreads();
    for (int off = 1; off < 1024; off <<= 1) {
        int t = (tid >= off) ? sm[tid - off] : 0;
        __syncthreads();
        sm[tid] += t;
        __syncthreads();
    }
    if (i < NN) offs[i + 1] = sm[tid];
    if (tid == 1023) part[blockIdx.x] = sm[1023];
}

// adds cross-block base (computed warp-parallel from part[]) and builds cursor
__global__ void k_scan3(int* offs, const int* __restrict__ part,
                        const int* __restrict__ counts, int* cursor) {
    __shared__ int base_s;
    int tid = threadIdx.x;
    if (tid < 32) {
        int b = 0;
        for (int j = tid; j < (int)blockIdx.x; j += 32) b += part[j];
#pragma unroll
        for (int o = 16; o > 0; o >>= 1) b += __shfl_xor_sync(~0u, b, o);
        if (tid == 0) base_s = b;
    }
    __syncthreads();
    int base = base_s;
    int i = blockIdx.x * 1024 + tid;
    if (i < NN) {
        int val = offs[i + 1] + base;
        offs[i + 1] = val;
        cursor[i] = val - counts[i];
    }
    if (i == 0) offs[0] = 0;
}

__global__ void k_scatter(const int* __restrict__ A, int* cursor, int* esrc) {
    int idx = blockIdx.x * 256 + threadIdx.x;
    if (idx >= ETOT) return;
    int s, d;
    if (idx < EE) { s = A[idx]; d = A[EE + idx]; }
    else          { s = idx - EE; d = s; }
    int pos = atomicAdd(&cursor[d], 1);
    esrc[pos] = s;
}

// ------------------------- tensor-core GEMM: h = x @ W (tf32 mma) --------------
__device__ __forceinline__ unsigned f2tf32(float f) {
    unsigned u;
    asm("cvt.rna.tf32.f32 %0, %1;" : "=r"(u) : "f"(f));
    return u;
}

// BM=128 rows/block, 256 threads (8 warps), BK=32, K=128 fixed.
template <int COLS>
__global__ __launch_bounds__(256) void gemm_tc(const float* __restrict__ X,
                                               const float* __restrict__ W,
                                               float* __restrict__ Hout,
                                               __half* __restrict__ Hh) {
    constexpr int BM = 128, BK = 32;
    constexpr int WM = (COLS == 128) ? 4 : 8;
    constexpr int MF = BM / (WM * 16);
    constexpr int NF = 8;
    constexpr int APAD = BK + 4;
    constexpr int WPAD = COLS + 8;

    __shared__ float As[BM][APAD];
    __shared__ float Ws[BK][WPAD];

    const int t = threadIdx.x;
    const int lane = t & 31;
    const int wid = t >> 5;
    const int wm = wid % WM;
    const int wn = wid / WM;
    const int row0 = blockIdx.x * BM;
    const int g = lane >> 2;
    const int q4 = lane & 3;

    float acc[MF][NF][4];
#pragma unroll
    for (int mf = 0; mf < MF; mf++)
#pragma unroll
        for (int nf = 0; nf < NF; nf++)
#pragma unroll
            for (int i = 0; i < 4; i++) acc[mf][nf][i] = 0.f;

#pragma unroll 1
    for (int kt = 0; kt < DIN_; kt += BK) {
        {
            constexpr int NV = BK * COLS / 4 / 256;
            const float4* Wg = reinterpret_cast<const float4*>(W + kt * COLS);
#pragma unroll
            for (int i = 0; i < NV; i++) {
                int qq = t + i * 256;
                int r = qq / (COLS / 4), c = qq % (COLS / 4);
                float4 v = Wg[qq];
                uint4 u = make_uint4(f2tf32(v.x), f2tf32(v.y), f2tf32(v.z), f2tf32(v.w));
                *reinterpret_cast<uint4*>(&Ws[r][c * 4]) = u;
            }
        }
        {
#pragma unroll
            for (int i = 0; i < 4; i++) {
                int qq = t + i * 256;
                int r = qq >> 3, c = qq & 7;
                int gr = row0 + r;
                float4 v = make_float4(0.f, 0.f, 0.f, 0.f);
                if (gr < NN)
                    v = reinterpret_cast<const float4*>(X + gr * DIN_ + kt)[c];
                uint4 u = make_uint4(f2tf32(v.x), f2tf32(v.y), f2tf32(v.z), f2tf32(v.w));
                *reinterpret_cast<uint4*>(&As[r][c * 4]) = u;
            }
        }
        __syncthreads();
#pragma unroll
        for (int k8 = 0; k8 < BK; k8 += 8) {
            unsigned a[MF][4];
#pragma unroll
            for (int mf = 0; mf < MF; mf++) {
                int r = wm * (MF * 16) + mf * 16 + g;
                a[mf][0] = __float_as_uint(As[r][k8 + q4]);
                a[mf][1] = __float_as_uint(As[r + 8][k8 + q4]);
                a[mf][2] = __float_as_uint(As[r][k8 + q4 + 4]);
                a[mf][3] = __float_as_uint(As[r + 8][k8 + q4 + 4]);
            }
            unsigned b[NF][2];
#pragma unroll
            for (int nf = 0; nf < NF; nf++) {
                int c = wn * 64 + nf * 8 + g;
                b[nf][0] = __float_as_uint(Ws[k8 + q4][c]);
                b[nf][1] = __float_as_uint(Ws[k8 + q4 + 4][c]);
            }
#pragma unroll
            for (int mf = 0; mf < MF; mf++)
#pragma unroll
                for (int nf = 0; nf < NF; nf++)
                    asm volatile(
                        "mma.sync.aligned.m16n8k8.row.col.f32.tf32.tf32.f32 "
                        "{%0,%1,%2,%3}, {%4,%5,%6,%7}, {%8,%9}, {%0,%1,%2,%3};"
                        : "+f"(acc[mf][nf][0]), "+f"(acc[mf][nf][1]),
                          "+f"(acc[mf][nf][2]), "+f"(acc[mf][nf][3])
                        : "r"(a[mf][0]), "r"(a[mf][1]), "r"(a[mf][2]), "r"(a[mf][3]),
                          "r"(b[nf][0]), "r"(b[nf][1]));
        }
        __syncthreads();
    }

#pragma unroll
    for (int mf = 0; mf < MF; mf++) {
        int r = row0 + wm * (MF * 16) + mf * 16 + g;
#pragma unroll
        for (int nf = 0; nf < NF; nf++) {
            int c = wn * 64 + nf * 8 + 2 * q4;
            if (r < NN) {
                float2 v = make_float2(acc[mf][nf][0], acc[mf][nf][1]);
                *reinterpret_cast<float2*>(&Hout[r * COLS + c]) = v;
                *reinterpret_cast<__half2*>(&Hh[r * COLS + c]) = __floats2half2_rn(v.x, v.y);
            }
            if (r + 8 < NN) {
                float2 v = make_float2(acc[mf][nf][2], acc[mf][nf][3]);
                *reinterpret_cast<float2*>(&Hout[(r + 8) * COLS + c]) = v;
                *reinterpret_cast<__half2*>(&Hh[(r + 8) * COLS + c]) = __floats2half2_rn(v.x, v.y);
            }
        }
    }
}

// ------------------------- attention logits per node ---------------------------
template <int H, int F>
__global__ __launch_bounds__(256) void attn_k(const float* __restrict__ Hb,
                                              const float* __restrict__ a_s,
                                              const float* __restrict__ a_d,
                                              float* __restrict__ ASRC,
                                              float* __restrict__ ADST) {
    int n = blockIdx.x * 8 + (threadIdx.x >> 5);
    if (n >= NN) return;
    int lane = threadIdx.x & 31;
    if constexpr (H * F == 128) {
        float4 hv = reinterpret_cast<const float4*>(Hb)[n * 32 + lane];
        int head = lane >> 2;
        int f0 = (lane & 3) * 4;
        const float* a = &a_s[head * F + f0];
        const float* d = &a_d[head * F + f0];
        float ps = hv.x * a[0] + hv.y * a[1] + hv.z * a[2] + hv.w * a[3];
        float pd = hv.x * d[0] + hv.y * d[1] + hv.z * d[2] + hv.w * d[3];
        ps += __shfl_xor_sync(~0u, ps, 1); ps += __shfl_xor_sync(~0u, ps, 2);
        pd += __shfl_xor_sync(~0u, pd, 1); pd += __shfl_xor_sync(~0u, pd, 2);
        if ((lane & 3) == 0) { ASRC[n * H + head] = ps; ADST[n * H + head] = pd; }
    } else {  // H*F == 64
        float2 hv = reinterpret_cast<const float2*>(Hb)[n * 32 + lane];
        int head = lane >> 3;
        int f0 = (lane & 7) * 2;
        float ps = hv.x * a_s[head * F + f0] + hv.y * a_s[head * F + f0 + 1];
        float pd = hv.x * a_d[head * F + f0] + hv.y * a_d[head * F + f0 + 1];
        ps += __shfl_xor_sync(~0u, ps, 1); ps += __shfl_xor_sync(~0u, ps, 2);
        ps += __shfl_xor_sync(~0u, ps, 4);
        pd += __shfl_xor_sync(~0u, pd, 1); pd += __shfl_xor_sync(~0u, pd, 2);
        pd += __shfl_xor_sync(~0u, pd, 4);
        if ((lane & 7) == 0) { ASRC[n * H + head] = ps; ADST[n * H + head] = pd; }
    }
}

// ------------------------- warp-per-node aggregation (direct exp) --------------
// No max subtraction: logits are O(1), exp is safe in fp32, result identical.
// Rolled loop + unroll 4: ptxas front-batches the independent LDGs (MLP ~8).
template <int H, int F, bool RELU, bool MEAN>
__global__ __launch_bounds__(256) void agg_k(const __half* __restrict__ Hh,
                                             const float* __restrict__ ASRC,
                                             const float* __restrict__ ADST,
                                             const int* __restrict__ esrc,
                                             const int* __restrict__ offs,
                                             const float* __restrict__ bias,
                                             float* __restrict__ out) {
    constexpr int HF = H * F;
    constexpr int VEC = HF / 32;
    int n = blockIdx.x * 8 + (threadIdx.x >> 5);
    if (n >= NN) return;
    int lane = threadIdx.x & 31;
    const int head = (lane * VEC) / F;

    const float adn = ADST[n * H + head];
    float s = 0.f;
    float acc[VEC];
#pragma unroll
    for (int v = 0; v < VEC; v++) acc[v] = 0.f;

    const int e0 = offs[n];
    const int end = offs[n + 1];

#pragma unroll 4
    for (int e = e0; e < end; e++) {
        int src = esrc[e];
        float ea = ASRC[src * H + head];
        float hv[VEC];
        if constexpr (VEC == 4) {
            uint2 u = reinterpret_cast<const uint2*>(Hh)[src * 32 + lane];
            float2 lo = __half22float2(*reinterpret_cast<__half2*>(&u.x));
            float2 hi = __half22float2(*reinterpret_cast<__half2*>(&u.y));
            hv[0] = lo.x; hv[1] = lo.y; hv[2] = hi.x; hv[3] = hi.y;
        } else {
            unsigned u = reinterpret_cast<const unsigned*>(Hh)[src * 32 + lane];
            float2 lo = __half22float2(*reinterpret_cast<__half2*>(&u));
            hv[0] = lo.x; hv[1] = lo.y;
        }
        float ev = ea + adn;
        ev = ev > 0.f ? ev : 0.2f * ev;   // leaky relu
        float p = __expf(ev);
        s += p;
#pragma unroll
        for (int v = 0; v < VEC; v++) acc[v] = fmaf(p, hv[v], acc[v]);
    }

    const float inv = 1.f / (s + 1e-16f);
    if constexpr (!MEAN) {
        float4 o;
        o.x = acc[0] * inv + bias[lane * 4 + 0];
        o.y = acc[1] * inv + bias[lane * 4 + 1];
        o.z = acc[2] * inv + bias[lane * 4 + 2];
        o.w = acc[3] * inv + bias[lane * 4 + 3];
        if (RELU) {
            o.x = fmaxf(o.x, 0.f); o.y = fmaxf(o.y, 0.f);
            o.z = fmaxf(o.z, 0.f); o.w = fmaxf(o.w, 0.f);
        }
        reinterpret_cast<float4*>(out)[n * 32 + lane] = o;
    } else {
        float ox = acc[0] * inv;
        float oy = acc[1] * inv;
        ox += __shfl_xor_sync(~0u, ox, 8);
        oy += __shfl_xor_sync(~0u, oy, 8);
        ox += __shfl_xor_sync(~0u, ox, 16);
        oy += __shfl_xor_sync(~0u, oy, 16);
        if (lane < 8) {
            out[n * 16 + 2 * lane]     = 0.25f * ox + bias[2 * lane];
            out[n * 16 + 2 * lane + 1] = 0.25f * oy + bias[2 * lane + 1];
        }
    }
}

// ------------------------- launcher -------------------------------------------
extern "C" void kernel_launch(void* const* d_in, const int* in_sizes, int n_in,
                              void* d_out, int out_size) {
    const float* X   = (const float*)d_in[0];
    const int*   A   = (const int*)d_in[1];
    const float* W1  = (const float*)d_in[2];
    const float* as1 = (const float*)d_in[3];
    const float* ad1 = (const float*)d_in[4];
    const float* b1  = (const float*)d_in[5];
    const float* W2  = (const float*)d_in[6];
    const float* as2 = (const float*)d_in[7];
    const float* ad2 = (const float*)d_in[8];
    const float* b2  = (const float*)d_in[9];
    const float* W3  = (const float*)d_in[10];
    const float* as3 = (const float*)d_in[11];
    const float* ad3 = (const float*)d_in[12];
    const float* b3  = (const float*)d_in[13];
    float* out = (float*)d_out;

    void* p;
    float *h, *x, *asb, *adb;
    __half* hh;
    int *counts, *offs, *cursor, *esrc, *part;
    cudaGetSymbolAddress(&p, g_h);      h = (float*)p;
    cudaGetSymbolAddress(&p, g_hh);     hh = (__half*)p;
    cudaGetSymbolAddress(&p, g_x);      x = (float*)p;
    cudaGetSymbolAddress(&p, g_as);     asb = (float*)p;
    cudaGetSymbolAddress(&p, g_ad);     adb = (float*)p;
    cudaGetSymbolAddress(&p, g_counts); counts = (int*)p;
    cudaGetSymbolAddress(&p, g_offs);   offs = (int*)p;
    cudaGetSymbolAddress(&p, g_cursor); cursor = (int*)p;
    cudaGetSymbolAddress(&p, g_esrc);   esrc = (int*)p;
    cudaGetSymbolAddress(&p, g_part);   part = (int*)p;

    const int NB = (NN + 1023) / 1024;  // 49

    // CSR by dst (counting sort), rebuilt every call (deterministic work)
    k_init<<<(NN + 255) / 256, 256>>>(counts);
    k_hist<<<(EE + 255) / 256, 256>>>(A, counts);
    k_scan1<<<NB, 1024>>>(counts, offs, part);
    k_scan3<<<NB, 1024>>>(offs, part, counts, cursor);
    k_scatter<<<(ETOT + 255) / 256, 256>>>(A, cursor, esrc);

    const int GB = (NN + 127) / 128;  // 391 blocks
    const int AB = (NN + 7) / 8;      // warp-per-node blocks

    // Layer 1
    gemm_tc<128><<<GB, 256>>>(X, W1, h, hh);
    attn_k<8, 16><<<AB, 256>>>(h, as1, ad1, asb, adb);
    agg_k<8, 16, true, false><<<AB, 256>>>(hh, asb, adb, esrc, offs, b1, x);
    // Layer 2
    gemm_tc<128><<<GB, 256>>>(x, W2, h, hh);
    attn_k<8, 16><<<AB, 256>>>(h, as2, ad2, asb, adb);
    agg_k<8, 16, true, false><<<AB, 256>>>(hh, asb, adb, esrc, offs, b2, x);
    // Layer 3 (mean over heads)
    gemm_tc<64><<<GB, 256>>>(x, W3, h, hh);
    attn_k<4, 16><<<AB, 256>>>(h, as3, ad3, asb, adb);
    agg_k<4, 16, false, true><<<AB, 256>>>(hh, asb, adb, esrc, offs, b3, out);
}

// round 6
// speedup vs baseline: 2.3341x; 1.0909x over previous
#include <cuda_runtime.h>
#include <cuda_fp16.h>
#include <math.h>

#define NN   50000
#define EE   1600000
#define ETOT 1650000
#define DIN_ 128

// ------------------------- device scratch (no allocs) -------------------------
__device__ __half g_hh[NN * 128];     // fp16 transformed features (edge gather)
__device__ float  g_x[NN * 128];      // layer activations
__device__ float  g_as[NN * 8];       // per-node src attention logits
__device__ float  g_ad[NN * 8];       // per-node dst attention logits
__device__ int    g_counts[NN];
__device__ int    g_offs[NN + 1];
__device__ int    g_cursor[NN];
__device__ int    g_esrc[ETOT];
__device__ int    g_part[64];

// ------------------------- CSR build ------------------------------------------
__global__ void k_init(int* counts) {
    int i = blockIdx.x * 256 + threadIdx.x;
    if (i < NN) counts[i] = 1;  // self-loop
}

__global__ void k_hist(const int* __restrict__ A, int* counts) {
    int e = blockIdx.x * 256 + threadIdx.x;
    if (e < EE) atomicAdd(&counts[A[EE + e]], 1);
}

__global__ void k_scan1(const int* __restrict__ counts, int* offs, int* part) {
    __shared__ int sm[1024];
    int tid = threadIdx.x;
    int i = blockIdx.x * 1024 + tid;
    int v = (i < NN) ? counts[i] : 0;
    sm[tid] = v;
    __syncthreads();
    for (int off = 1; off < 1024; off <<= 1) {
        int t = (tid >= off) ? sm[tid - off] : 0;
        __syncthreads();
        sm[tid] += t;
        __syncthreads();
    }
    if (i < NN) offs[i + 1] = sm[tid];
    if (tid == 1023) part[blockIdx.x] = sm[1023];
}

// adds cross-block base (warp-parallel over part[]) and builds cursor
__global__ void k_scan3(int* offs, const int* __restrict__ part,
                        const int* __restrict__ counts, int* cursor) {
    __shared__ int base_s;
    int tid = threadIdx.x;
    if (tid < 32) {
        int b = 0;
        for (int j = tid; j < (int)blockIdx.x; j += 32) b += part[j];
#pragma unroll
        for (int o = 16; o > 0; o >>= 1) b += __shfl_xor_sync(~0u, b, o);
        if (tid == 0) base_s = b;
    }
    __syncthreads();
    int base = base_s;
    int i = blockIdx.x * 1024 + tid;
    if (i < NN) {
        int val = offs[i + 1] + base;
        offs[i + 1] = val;
        cursor[i] = val - counts[i];
    }
    if (i == 0) offs[0] = 0;
}

__global__ void k_scatter(const int* __restrict__ A, int* cursor, int* esrc) {
    int idx = blockIdx.x * 256 + threadIdx.x;
    if (idx >= ETOT) return;
    int s, d;
    if (idx < EE) { s = A[idx]; d = A[EE + idx]; }
    else          { s = idx - EE; d = s; }
    int pos = atomicAdd(&cursor[d], 1);
    esrc[pos] = s;
}

// ------------------------- tensor-core GEMM + fused attn logits ----------------
__device__ __forceinline__ unsigned f2tf32(float f) {
    unsigned u;
    asm("cvt.rna.tf32.f32 %0, %1;" : "=r"(u) : "f"(f));
    return u;
}

// BM=128 rows/block, 256 threads (8 warps), BK=32, K=128 fixed.
// Epilogue: writes fp16 h; computes per-node attention logits from the fp32
// accumulators (per-head dot with a_src/a_dst), reduced across q4 lanes.
template <int COLS>
__global__ __launch_bounds__(256) void gemm_tc(const float* __restrict__ X,
                                               const float* __restrict__ W,
                                               const float* __restrict__ a_s,
                                               const float* __restrict__ a_d,
                                               __half* __restrict__ Hh,
                                               float* __restrict__ ASRC,
                                               float* __restrict__ ADST) {
    constexpr int BM = 128, BK = 32;
    constexpr int WM = (COLS == 128) ? 4 : 8;
    constexpr int MF = BM / (WM * 16);
    constexpr int NF = 8;
    constexpr int APAD = BK + 4;
    constexpr int WPAD = COLS + 8;
    constexpr int H = COLS / 16;          // heads total (8 or 4)

    __shared__ float As[BM][APAD];
    __shared__ float Ws[BK][WPAD];
    __shared__ float as_sm[COLS], ad_sm[COLS];

    const int t = threadIdx.x;
    const int lane = t & 31;
    const int wid = t >> 5;
    const int wm = wid % WM;
    const int wn = wid / WM;
    const int row0 = blockIdx.x * BM;
    const int g = lane >> 2;
    const int q4 = lane & 3;

    if (t < COLS) { as_sm[t] = a_s[t]; ad_sm[t] = a_d[t]; }

    float acc[MF][NF][4];
#pragma unroll
    for (int mf = 0; mf < MF; mf++)
#pragma unroll
        for (int nf = 0; nf < NF; nf++)
#pragma unroll
            for (int i = 0; i < 4; i++) acc[mf][nf][i] = 0.f;

#pragma unroll 1
    for (int kt = 0; kt < DIN_; kt += BK) {
        {
            constexpr int NV = BK * COLS / 4 / 256;
            const float4* Wg = reinterpret_cast<const float4*>(W + kt * COLS);
#pragma unroll
            for (int i = 0; i < NV; i++) {
                int qq = t + i * 256;
                int r = qq / (COLS / 4), c = qq % (COLS / 4);
                float4 v = Wg[qq];
                uint4 u = make_uint4(f2tf32(v.x), f2tf32(v.y), f2tf32(v.z), f2tf32(v.w));
                *reinterpret_cast<uint4*>(&Ws[r][c * 4]) = u;
            }
        }
        {
#pragma unroll
            for (int i = 0; i < 4; i++) {
                int qq = t + i * 256;
                int r = qq >> 3, c = qq & 7;
                int gr = row0 + r;
                float4 v = make_float4(0.f, 0.f, 0.f, 0.f);
                if (gr < NN)
                    v = reinterpret_cast<const float4*>(X + gr * DIN_ + kt)[c];
                uint4 u = make_uint4(f2tf32(v.x), f2tf32(v.y), f2tf32(v.z), f2tf32(v.w));
                *reinterpret_cast<uint4*>(&As[r][c * 4]) = u;
            }
        }
        __syncthreads();
#pragma unroll
        for (int k8 = 0; k8 < BK; k8 += 8) {
            unsigned a[MF][4];
#pragma unroll
            for (int mf = 0; mf < MF; mf++) {
                int r = wm * (MF * 16) + mf * 16 + g;
                a[mf][0] = __float_as_uint(As[r][k8 + q4]);
                a[mf][1] = __float_as_uint(As[r + 8][k8 + q4]);
                a[mf][2] = __float_as_uint(As[r][k8 + q4 + 4]);
                a[mf][3] = __float_as_uint(As[r + 8][k8 + q4 + 4]);
            }
            unsigned b[NF][2];
#pragma unroll
            for (int nf = 0; nf < NF; nf++) {
                int c = wn * 64 + nf * 8 + g;
                b[nf][0] = __float_as_uint(Ws[k8 + q4][c]);
                b[nf][1] = __float_as_uint(Ws[k8 + q4 + 4][c]);
            }
#pragma unroll
            for (int mf = 0; mf < MF; mf++)
#pragma unroll
                for (int nf = 0; nf < NF; nf++)
                    asm volatile(
                        "mma.sync.aligned.m16n8k8.row.col.f32.tf32.tf32.f32 "
                        "{%0,%1,%2,%3}, {%4,%5,%6,%7}, {%8,%9}, {%0,%1,%2,%3};"
                        : "+f"(acc[mf][nf][0]), "+f"(acc[mf][nf][1]),
                          "+f"(acc[mf][nf][2]), "+f"(acc[mf][nf][3])
                        : "r"(a[mf][0]), "r"(a[mf][1]), "r"(a[mf][2]), "r"(a[mf][3]),
                          "r"(b[nf][0]), "r"(b[nf][1]));
        }
        __syncthreads();
    }

    // epilogue: fp16 h stores + per-head attention logit partials
#pragma unroll
    for (int mf = 0; mf < MF; mf++) {
        int r = row0 + wm * (MF * 16) + mf * 16 + g;
        float psA[4] = {0, 0, 0, 0}, pdA[4] = {0, 0, 0, 0};
        float psB[4] = {0, 0, 0, 0}, pdB[4] = {0, 0, 0, 0};
#pragma unroll
        for (int nf = 0; nf < NF; nf++) {
            int c = wn * 64 + nf * 8 + 2 * q4;
            int hl = nf >> 1;
            float sa0 = as_sm[c], sa1 = as_sm[c + 1];
            float da0 = ad_sm[c], da1 = ad_sm[c + 1];
            psA[hl] += acc[mf][nf][0] * sa0 + acc[mf][nf][1] * sa1;
            pdA[hl] += acc[mf][nf][0] * da0 + acc[mf][nf][1] * da1;
            psB[hl] += acc[mf][nf][2] * sa0 + acc[mf][nf][3] * sa1;
            pdB[hl] += acc[mf][nf][2] * da0 + acc[mf][nf][3] * da1;
            if (r < NN)
                *reinterpret_cast<__half2*>(&Hh[r * COLS + c]) =
                    __floats2half2_rn(acc[mf][nf][0], acc[mf][nf][1]);
            if (r + 8 < NN)
                *reinterpret_cast<__half2*>(&Hh[(r + 8) * COLS + c]) =
                    __floats2half2_rn(acc[mf][nf][2], acc[mf][nf][3]);
        }
        // reduce over the 4 q4 lanes (lane bits 0,1)
#pragma unroll
        for (int hl = 0; hl < 4; hl++) {
            psA[hl] += __shfl_xor_sync(~0u, psA[hl], 1);
            psA[hl] += __shfl_xor_sync(~0u, psA[hl], 2);
            pdA[hl] += __shfl_xor_sync(~0u, pdA[hl], 1);
            pdA[hl] += __shfl_xor_sync(~0u, pdA[hl], 2);
            psB[hl] += __shfl_xor_sync(~0u, psB[hl], 1);
            psB[hl] += __shfl_xor_sync(~0u, psB[hl], 2);
            pdB[hl] += __shfl_xor_sync(~0u, pdB[hl], 1);
            pdB[hl] += __shfl_xor_sync(~0u, pdB[hl], 2);
        }
        if (q4 == 0) {
            if (r < NN) {
                *reinterpret_cast<float4*>(&ASRC[r * H + wn * 4]) =
                    make_float4(psA[0], psA[1], psA[2], psA[3]);
                *reinterpret_cast<float4*>(&ADST[r * H + wn * 4]) =
                    make_float4(pdA[0], pdA[1], pdA[2], pdA[3]);
            }
            if (r + 8 < NN) {
                *reinterpret_cast<float4*>(&ASRC[(r + 8) * H + wn * 4]) =
                    make_float4(psB[0], psB[1], psB[2], psB[3]);
                *reinterpret_cast<float4*>(&ADST[(r + 8) * H + wn * 4]) =
                    make_float4(pdB[0], pdB[1], pdB[2], pdB[3]);
            }
        }
    }
}

// ------------------------- warp-per-node aggregation (direct exp) --------------
template <int H, int F, bool RELU, bool MEAN>
__global__ __launch_bounds__(256) void agg_k(const __half* __restrict__ Hh,
                                             const float* __restrict__ ASRC,
                                             const float* __restrict__ ADST,
                                             const int* __restrict__ esrc,
                                             const int* __restrict__ offs,
                                             const float* __restrict__ bias,
                                             float* __restrict__ out) {
    constexpr int HF = H * F;
    constexpr int VEC = HF / 32;
    int n = blockIdx.x * 8 + (threadIdx.x >> 5);
    if (n >= NN) return;
    int lane = threadIdx.x & 31;
    const int head = (lane * VEC) / F;

    const float adn = ADST[n * H + head];
    float s = 0.f;
    float acc[VEC];
#pragma unroll
    for (int v = 0; v < VEC; v++) acc[v] = 0.f;

    const int e0 = offs[n];
    const int end = offs[n + 1];

#pragma unroll 4
    for (int e = e0; e < end; e++) {
        int src = esrc[e];
        float ea = ASRC[src * H + head];
        float hv[VEC];
        if constexpr (VEC == 4) {
            uint2 u = reinterpret_cast<const uint2*>(Hh)[src * 32 + lane];
            float2 lo = __half22float2(*reinterpret_cast<__half2*>(&u.x));
            float2 hi = __half22float2(*reinterpret_cast<__half2*>(&u.y));
            hv[0] = lo.x; hv[1] = lo.y; hv[2] = hi.x; hv[3] = hi.y;
        } else {
            unsigned u = reinterpret_cast<const unsigned*>(Hh)[src * 32 + lane];
            float2 lo = __half22float2(*reinterpret_cast<__half2*>(&u));
            hv[0] = lo.x; hv[1] = lo.y;
        }
        float ev = ea + adn;
        ev = ev > 0.f ? ev : 0.2f * ev;   // leaky relu
        float p = __expf(ev);
        s += p;
#pragma unroll
        for (int v = 0; v < VEC; v++) acc[v] = fmaf(p, hv[v], acc[v]);
    }

    const float inv = 1.f / (s + 1e-16f);
    if constexpr (!MEAN) {
        float4 o;
        o.x = acc[0] * inv + bias[lane * 4 + 0];
        o.y = acc[1] * inv + bias[lane * 4 + 1];
        o.z = acc[2] * inv + bias[lane * 4 + 2];
        o.w = acc[3] * inv + bias[lane * 4 + 3];
        if (RELU) {
            o.x = fmaxf(o.x, 0.f); o.y = fmaxf(o.y, 0.f);
            o.z = fmaxf(o.z, 0.f); o.w = fmaxf(o.w, 0.f);
        }
        reinterpret_cast<float4*>(out)[n * 32 + lane] = o;
    } else {
        float ox = acc[0] * inv;
        float oy = acc[1] * inv;
        ox += __shfl_xor_sync(~0u, ox, 8);
        oy += __shfl_xor_sync(~0u, oy, 8);
        ox += __shfl_xor_sync(~0u, ox, 16);
        oy += __shfl_xor_sync(~0u, oy, 16);
        if (lane < 8) {
            out[n * 16 + 2 * lane]     = 0.25f * ox + bias[2 * lane];
            out[n * 16 + 2 * lane + 1] = 0.25f * oy + bias[2 * lane + 1];
        }
    }
}

// ------------------------- launcher -------------------------------------------
extern "C" void kernel_launch(void* const* d_in, const int* in_sizes, int n_in,
                              void* d_out, int out_size) {
    const float* X   = (const float*)d_in[0];
    const int*   A   = (const int*)d_in[1];
    const float* W1  = (const float*)d_in[2];
    const float* as1 = (const float*)d_in[3];
    const float* ad1 = (const float*)d_in[4];
    const float* b1  = (const float*)d_in[5];
    const float* W2  = (const float*)d_in[6];
    const float* as2 = (const float*)d_in[7];
    const float* ad2 = (const float*)d_in[8];
    const float* b2  = (const float*)d_in[9];
    const float* W3  = (const float*)d_in[10];
    const float* as3 = (const float*)d_in[11];
    const float* ad3 = (const float*)d_in[12];
    const float* b3  = (const float*)d_in[13];
    float* out = (float*)d_out;

    void* p;
    float *x, *asb, *adb;
    __half* hh;
    int *counts, *offs, *cursor, *esrc, *part;
    cudaGetSymbolAddress(&p, g_hh);     hh = (__half*)p;
    cudaGetSymbolAddress(&p, g_x);      x = (float*)p;
    cudaGetSymbolAddress(&p, g_as);     asb = (float*)p;
    cudaGetSymbolAddress(&p, g_ad);     adb = (float*)p;
    cudaGetSymbolAddress(&p, g_counts); counts = (int*)p;
    cudaGetSymbolAddress(&p, g_offs);   offs = (int*)p;
    cudaGetSymbolAddress(&p, g_cursor); cursor = (int*)p;
    cudaGetSymbolAddress(&p, g_esrc);   esrc = (int*)p;
    cudaGetSymbolAddress(&p, g_part);   part = (int*)p;

    const int NB = (NN + 1023) / 1024;  // 49

    // CSR by dst (counting sort), rebuilt every call (deterministic work)
    k_init<<<(NN + 255) / 256, 256>>>(counts);
    k_hist<<<(EE + 255) / 256, 256>>>(A, counts);
    k_scan1<<<NB, 1024>>>(counts, offs, part);
    k_scan3<<<NB, 1024>>>(offs, part, counts, cursor);
    k_scatter<<<(ETOT + 255) / 256, 256>>>(A, cursor, esrc);

    const int GB = (NN + 127) / 128;  // 391 blocks
    const int AB = (NN + 7) / 8;      // warp-per-node blocks

    // Layer 1
    gemm_tc<128><<<GB, 256>>>(X, W1, as1, ad1, hh, asb, adb);
    agg_k<8, 16, true, false><<<AB, 256>>>(hh, asb, adb, esrc, offs, b1, x);
    // Layer 2
    gemm_tc<128><<<GB, 256>>>(x, W2, as2, ad2, hh, asb, adb);
    agg_k<8, 16, true, false><<<AB, 256>>>(hh, asb, adb, esrc, offs, b2, x);
    // Layer 3 (mean over heads)
    gemm_tc<64><<<GB, 256>>>(x, W3, as3, ad3, hh, asb, adb);
    agg_k<4, 16, false, true><<<AB, 256>>>(hh, asb, adb, esrc, offs, b3, out);
}

// round 7
// speedup vs baseline: 2.7137x; 1.1626x over previous
#include <cuda_runtime.h>
#include <cuda_fp16.h>
#include <math.h>

#define NN   50000
#define EE   1600000
#define ETOT 1650000
#define DIN_ 128

// ------------------------- device scratch (no allocs) -------------------------
__device__ __half g_hh[NN * 128];     // fp16 transformed features (edge gather)
__device__ float  g_x[NN * 128];      // layer activations
__device__ float  g_as[NN * 8];       // per-node src attention logits
__device__ float  g_ad[NN * 8];       // per-node dst attention logits
__device__ int    g_counts[NN];
__device__ int    g_offs[NN + 1];
__device__ int    g_cursor[NN];
__device__ int    g_esrc[ETOT];
__device__ int    g_part[64];

// ------------------------- CSR build ------------------------------------------
__global__ void k_init(int* counts) {
    int i = blockIdx.x * 256 + threadIdx.x;
    if (i < NN) counts[i] = 1;  // self-loop
}

__global__ void k_hist(const int* __restrict__ A, int* counts) {
    int e = blockIdx.x * 256 + threadIdx.x;
    if (e < EE) atomicAdd(&counts[A[EE + e]], 1);
}

__global__ void k_scan1(const int* __restrict__ counts, int* offs, int* part) {
    __shared__ int sm[1024];
    int tid = threadIdx.x;
    int i = blockIdx.x * 1024 + tid;
    int v = (i < NN) ? counts[i] : 0;
    sm[tid] = v;
    __syncthreads();
    for (int off = 1; off < 1024; off <<= 1) {
        int t = (tid >= off) ? sm[tid - off] : 0;
        __syncthreads();
        sm[tid] += t;
        __syncthreads();
    }
    if (i < NN) offs[i + 1] = sm[tid];
    if (tid == 1023) part[blockIdx.x] = sm[1023];
}

__global__ void k_scan3(int* offs, const int* __restrict__ part,
                        const int* __restrict__ counts, int* cursor) {
    __shared__ int base_s;
    int tid = threadIdx.x;
    if (tid < 32) {
        int b = 0;
        for (int j = tid; j < (int)blockIdx.x; j += 32) b += part[j];
#pragma unroll
        for (int o = 16; o > 0; o >>= 1) b += __shfl_xor_sync(~0u, b, o);
        if (tid == 0) base_s = b;
    }
    __syncthreads();
    int base = base_s;
    int i = blockIdx.x * 1024 + tid;
    if (i < NN) {
        int val = offs[i + 1] + base;
        offs[i + 1] = val;
        cursor[i] = val - counts[i];
    }
    if (i == 0) offs[0] = 0;
}

__global__ void k_scatter(const int* __restrict__ A, int* cursor, int* esrc) {
    int idx = blockIdx.x * 256 + threadIdx.x;
    if (idx >= ETOT) return;
    int s, d;
    if (idx < EE) { s = A[idx]; d = A[EE + idx]; }
    else          { s = idx - EE; d = s; }
    int pos = atomicAdd(&cursor[d], 1);
    esrc[pos] = s;
}

// ------------------------- tensor-core GEMM + fused attn logits ----------------
__device__ __forceinline__ unsigned f2tf32(float f) {
    unsigned u;
    asm("cvt.rna.tf32.f32 %0, %1;" : "=r"(u) : "f"(f));
    return u;
}

template <int COLS>
__global__ __launch_bounds__(256) void gemm_tc(const float* __restrict__ X,
                                               const float* __restrict__ W,
                                               const float* __restrict__ a_s,
                                               const float* __restrict__ a_d,
                                               __half* __restrict__ Hh,
                                               float* __restrict__ ASRC,
                                               float* __restrict__ ADST) {
    constexpr int BM = 128, BK = 32;
    constexpr int WM = (COLS == 128) ? 4 : 8;
    constexpr int MF = BM / (WM * 16);
    constexpr int NF = 8;
    constexpr int APAD = BK + 4;
    constexpr int WPAD = COLS + 8;
    constexpr int H = COLS / 16;

    __shared__ float As[BM][APAD];
    __shared__ float Ws[BK][WPAD];
    __shared__ float as_sm[COLS], ad_sm[COLS];

    const int t = threadIdx.x;
    const int lane = t & 31;
    const int wid = t >> 5;
    const int wm = wid % WM;
    const int wn = wid / WM;
    const int row0 = blockIdx.x * BM;
    const int g = lane >> 2;
    const int q4 = lane & 3;

    if (t < COLS) { as_sm[t] = a_s[t]; ad_sm[t] = a_d[t]; }

    float acc[MF][NF][4];
#pragma unroll
    for (int mf = 0; mf < MF; mf++)
#pragma unroll
        for (int nf = 0; nf < NF; nf++)
#pragma unroll
            for (int i = 0; i < 4; i++) acc[mf][nf][i] = 0.f;

#pragma unroll 1
    for (int kt = 0; kt < DIN_; kt += BK) {
        {
            constexpr int NV = BK * COLS / 4 / 256;
            const float4* Wg = reinterpret_cast<const float4*>(W + kt * COLS);
#pragma unroll
            for (int i = 0; i < NV; i++) {
                int qq = t + i * 256;
                int r = qq / (COLS / 4), c = qq % (COLS / 4);
                float4 v = Wg[qq];
                uint4 u = make_uint4(f2tf32(v.x), f2tf32(v.y), f2tf32(v.z), f2tf32(v.w));
                *reinterpret_cast<uint4*>(&Ws[r][c * 4]) = u;
            }
        }
        {
#pragma unroll
            for (int i = 0; i < 4; i++) {
                int qq = t + i * 256;
                int r = qq >> 3, c = qq & 7;
                int gr = row0 + r;
                float4 v = make_float4(0.f, 0.f, 0.f, 0.f);
                if (gr < NN)
                    v = reinterpret_cast<const float4*>(X + gr * DIN_ + kt)[c];
                uint4 u = make_uint4(f2tf32(v.x), f2tf32(v.y), f2tf32(v.z), f2tf32(v.w));
                *reinterpret_cast<uint4*>(&As[r][c * 4]) = u;
            }
        }
        __syncthreads();
#pragma unroll
        for (int k8 = 0; k8 < BK; k8 += 8) {
            unsigned a[MF][4];
#pragma unroll
            for (int mf = 0; mf < MF; mf++) {
                int r = wm * (MF * 16) + mf * 16 + g;
                a[mf][0] = __float_as_uint(As[r][k8 + q4]);
                a[mf][1] = __float_as_uint(As[r + 8][k8 + q4]);
                a[mf][2] = __float_as_uint(As[r][k8 + q4 + 4]);
                a[mf][3] = __float_as_uint(As[r + 8][k8 + q4 + 4]);
            }
            unsigned b[NF][2];
#pragma unroll
            for (int nf = 0; nf < NF; nf++) {
                int c = wn * 64 + nf * 8 + g;
                b[nf][0] = __float_as_uint(Ws[k8 + q4][c]);
                b[nf][1] = __float_as_uint(Ws[k8 + q4 + 4][c]);
            }
#pragma unroll
            for (int mf = 0; mf < MF; mf++)
#pragma unroll
                for (int nf = 0; nf < NF; nf++)
                    asm volatile(
                        "mma.sync.aligned.m16n8k8.row.col.f32.tf32.tf32.f32 "
                        "{%0,%1,%2,%3}, {%4,%5,%6,%7}, {%8,%9}, {%0,%1,%2,%3};"
                        : "+f"(acc[mf][nf][0]), "+f"(acc[mf][nf][1]),
                          "+f"(acc[mf][nf][2]), "+f"(acc[mf][nf][3])
                        : "r"(a[mf][0]), "r"(a[mf][1]), "r"(a[mf][2]), "r"(a[mf][3]),
                          "r"(b[nf][0]), "r"(b[nf][1]));
        }
        __syncthreads();
    }

#pragma unroll
    for (int mf = 0; mf < MF; mf++) {
        int r = row0 + wm * (MF * 16) + mf * 16 + g;
        float psA[4] = {0, 0, 0, 0}, pdA[4] = {0, 0, 0, 0};
        float psB[4] = {0, 0, 0, 0}, pdB[4] = {0, 0, 0, 0};
#pragma unroll
        for (int nf = 0; nf < NF; nf++) {
            int c = wn * 64 + nf * 8 + 2 * q4;
            int hl = nf >> 1;
            float sa0 = as_sm[c], sa1 = as_sm[c + 1];
            float da0 = ad_sm[c], da1 = ad_sm[c + 1];
            psA[hl] += acc[mf][nf][0] * sa0 + acc[mf][nf][1] * sa1;
            pdA[hl] += acc[mf][nf][0] * da0 + acc[mf][nf][1] * da1;
            psB[hl] += acc[mf][nf][2] * sa0 + acc[mf][nf][3] * sa1;
            pdB[hl] += acc[mf][nf][2] * da0 + acc[mf][nf][3] * da1;
            if (r < NN)
                *reinterpret_cast<__half2*>(&Hh[r * COLS + c]) =
                    __floats2half2_rn(acc[mf][nf][0], acc[mf][nf][1]);
            if (r + 8 < NN)
                *reinterpret_cast<__half2*>(&Hh[(r + 8) * COLS + c]) =
                    __floats2half2_rn(acc[mf][nf][2], acc[mf][nf][3]);
        }
#pragma unroll
        for (int hl = 0; hl < 4; hl++) {
            psA[hl] += __shfl_xor_sync(~0u, psA[hl], 1);
            psA[hl] += __shfl_xor_sync(~0u, psA[hl], 2);
            pdA[hl] += __shfl_xor_sync(~0u, pdA[hl], 1);
            pdA[hl] += __shfl_xor_sync(~0u, pdA[hl], 2);
            psB[hl] += __shfl_xor_sync(~0u, psB[hl], 1);
            psB[hl] += __shfl_xor_sync(~0u, psB[hl], 2);
            pdB[hl] += __shfl_xor_sync(~0u, pdB[hl], 1);
            pdB[hl] += __shfl_xor_sync(~0u, pdB[hl], 2);
        }
        if (q4 == 0) {
            if (r < NN) {
                *reinterpret_cast<float4*>(&ASRC[r * H + wn * 4]) =
                    make_float4(psA[0], psA[1], psA[2], psA[3]);
                *reinterpret_cast<float4*>(&ADST[r * H + wn * 4]) =
                    make_float4(pdA[0], pdA[1], pdA[2], pdA[3]);
            }
            if (r + 8 < NN) {
                *reinterpret_cast<float4*>(&ASRC[(r + 8) * H + wn * 4]) =
                    make_float4(psB[0], psB[1], psB[2], psB[3]);
                *reinterpret_cast<float4*>(&ADST[(r + 8) * H + wn * 4]) =
                    make_float4(pdB[0], pdB[1], pdB[2], pdB[3]);
            }
        }
    }
}

// ------------- aggregation, HF=128: half-warp per edge, 2 edges/iter -----------
// lane: sub = l>>4 (edge), j = l&15 (8 features j*8..), head = j>>1.
template <bool RELU>
__global__ __launch_bounds__(256) void agg128_k(const __half* __restrict__ Hh,
                                                const float* __restrict__ ASRC,
                                                const float* __restrict__ ADST,
                                                const int* __restrict__ esrc,
                                                const int* __restrict__ offs,
                                                const float* __restrict__ bias,
                                                float* __restrict__ out) {
    int n = blockIdx.x * 8 + (threadIdx.x >> 5);
    if (n >= NN) return;
    const int lane = threadIdx.x & 31;
    const int sub = lane >> 4;
    const int j = lane & 15;
    const int head = j >> 1;

    const float adn = ADST[n * 8 + head];
    float s = 0.f;
    float acc[8];
#pragma unroll
    for (int v = 0; v < 8; v++) acc[v] = 0.f;

    const int e0 = offs[n];
    const int end = offs[n + 1];

#pragma unroll 2
    for (int e = e0; e < end; e += 2) {
        int ee = e + sub;
        int src = esrc[min(ee, end - 1)];
        float ea = ASRC[src * 8 + head];
        uint4 u = reinterpret_cast<const uint4*>(Hh)[src * 16 + j];
        float ev = ea + adn;
        ev = ev > 0.f ? ev : 0.2f * ev;
        float p = __expf(ev);
        p = (ee < end) ? p : 0.f;
        s += p;
        float2 f0 = __half22float2(*reinterpret_cast<__half2*>(&u.x));
        float2 f1 = __half22float2(*reinterpret_cast<__half2*>(&u.y));
        float2 f2 = __half22float2(*reinterpret_cast<__half2*>(&u.z));
        float2 f3 = __half22float2(*reinterpret_cast<__half2*>(&u.w));
        acc[0] = fmaf(p, f0.x, acc[0]); acc[1] = fmaf(p, f0.y, acc[1]);
        acc[2] = fmaf(p, f1.x, acc[2]); acc[3] = fmaf(p, f1.y, acc[3]);
        acc[4] = fmaf(p, f2.x, acc[4]); acc[5] = fmaf(p, f2.y, acc[5]);
        acc[6] = fmaf(p, f3.x, acc[6]); acc[7] = fmaf(p, f3.y, acc[7]);
    }

    // combine the two half-warps
    s += __shfl_xor_sync(~0u, s, 16);
#pragma unroll
    for (int v = 0; v < 8; v++) acc[v] += __shfl_xor_sync(~0u, acc[v], 16);

    const float inv = 1.f / (s + 1e-16f);
    if (sub == 0) {
        float4 o0, o1;
        o0.x = acc[0] * inv + bias[j * 8 + 0];
        o0.y = acc[1] * inv + bias[j * 8 + 1];
        o0.z = acc[2] * inv + bias[j * 8 + 2];
        o0.w = acc[3] * inv + bias[j * 8 + 3];
        o1.x = acc[4] * inv + bias[j * 8 + 4];
        o1.y = acc[5] * inv + bias[j * 8 + 5];
        o1.z = acc[6] * inv + bias[j * 8 + 6];
        o1.w = acc[7] * inv + bias[j * 8 + 7];
        if (RELU) {
            o0.x = fmaxf(o0.x, 0.f); o0.y = fmaxf(o0.y, 0.f);
            o0.z = fmaxf(o0.z, 0.f); o0.w = fmaxf(o0.w, 0.f);
            o1.x = fmaxf(o1.x, 0.f); o1.y = fmaxf(o1.y, 0.f);
            o1.z = fmaxf(o1.z, 0.f); o1.w = fmaxf(o1.w, 0.f);
        }
        reinterpret_cast<float4*>(out)[n * 32 + j * 2] = o0;
        reinterpret_cast<float4*>(out)[n * 32 + j * 2 + 1] = o1;
    }
}

// -------- aggregation, HF=64, mean over 4 heads: quarter-warp, 4 edges/iter ----
// lane: sub = l>>3 (edge 0-3), j = l&7 (8 features j*8..), head = j>>1.
__global__ __launch_bounds__(256) void agg64_mean_k(const __half* __restrict__ Hh,
                                                    const float* __restrict__ ASRC,
                                                    const float* __restrict__ ADST,
                                                    const int* __restrict__ esrc,
                                                    const int* __restrict__ offs,
                                                    const float* __restrict__ bias,
                                                    float* __restrict__ out) {
    int n = blockIdx.x * 8 + (threadIdx.x >> 5);
    if (n >= NN) return;
    const int lane = threadIdx.x & 31;
    const int sub = lane >> 3;
    const int j = lane & 7;
    const int head = j >> 1;

    const float adn = ADST[n * 4 + head];
    float s = 0.f;
    float acc[8];
#pragma unroll
    for (int v = 0; v < 8; v++) acc[v] = 0.f;

    const int e0 = offs[n];
    const int end = offs[n + 1];

#pragma unroll 2
    for (int e = e0; e < end; e += 4) {
        int ee = e + sub;
        int src = esrc[min(ee, end - 1)];
        float ea = ASRC[src * 4 + head];
        uint4 u = reinterpret_cast<const uint4*>(Hh)[src * 8 + j];
        float ev = ea + adn;
        ev = ev > 0.f ? ev : 0.2f * ev;
        float p = __expf(ev);
        p = (ee < end) ? p : 0.f;
        s += p;
        float2 f0 = __half22float2(*reinterpret_cast<__half2*>(&u.x));
        float2 f1 = __half22float2(*reinterpret_cast<__half2*>(&u.y));
        float2 f2 = __half22float2(*reinterpret_cast<__half2*>(&u.z));
        float2 f3 = __half22float2(*reinterpret_cast<__half2*>(&u.w));
        acc[0] = fmaf(p, f0.x, acc[0]); acc[1] = fmaf(p, f0.y, acc[1]);
        acc[2] = fmaf(p, f1.x, acc[2]); acc[3] = fmaf(p, f1.y, acc[3]);
        acc[4] = fmaf(p, f2.x, acc[4]); acc[5] = fmaf(p, f2.y, acc[5]);
        acc[6] = fmaf(p, f3.x, acc[6]); acc[7] = fmaf(p, f3.y, acc[7]);
    }

    // combine the four sub-groups (lane bits 3,4)
    s += __shfl_xor_sync(~0u, s, 8);
    s += __shfl_xor_sync(~0u, s, 16);
#pragma unroll
    for (int v = 0; v < 8; v++) {
        acc[v] += __shfl_xor_sync(~0u, acc[v], 8);
        acc[v] += __shfl_xor_sync(~0u, acc[v], 16);
    }
    // normalize per head, then mean over heads (lane bits 1,2 flip head bits)
    const float inv = 1.f / (s + 1e-16f);
#pragma unroll
    for (int v = 0; v < 8; v++) {
        acc[v] *= inv;
        acc[v] += __shfl_xor_sync(~0u, acc[v], 2);
        acc[v] += __shfl_xor_sync(~0u, acc[v], 4);
    }
    if (lane < 2) {  // lane 0: fi 0-7, lane 1: fi 8-15
        int fi = lane * 8;
        float4 o0, o1;
        o0.x = 0.25f * acc[0] + bias[fi + 0];
        o0.y = 0.25f * acc[1] + bias[fi + 1];
        o0.z = 0.25f * acc[2] + bias[fi + 2];
        o0.w = 0.25f * acc[3] + bias[fi + 3];
        o1.x = 0.25f * acc[4] + bias[fi + 4];
        o1.y = 0.25f * acc[5] + bias[fi + 5];
        o1.z = 0.25f * acc[6] + bias[fi + 6];
        o1.w = 0.25f * acc[7] + bias[fi + 7];
        reinterpret_cast<float4*>(out)[n * 4 + lane * 2] = o0;
        reinterpret_cast<float4*>(out)[n * 4 + lane * 2 + 1] = o1;
    }
}

// ------------------------- launcher -------------------------------------------
extern "C" void kernel_launch(void* const* d_in, const int* in_sizes, int n_in,
                              void* d_out, int out_size) {
    const float* X   = (const float*)d_in[0];
    const int*   A   = (const int*)d_in[1];
    const float* W1  = (const float*)d_in[2];
    const float* as1 = (const float*)d_in[3];
    const float* ad1 = (const float*)d_in[4];
    const float* b1  = (const float*)d_in[5];
    const float* W2  = (const float*)d_in[6];
    const float* as2 = (const float*)d_in[7];
    const float* ad2 = (const float*)d_in[8];
    const float* b2  = (const float*)d_in[9];
    const float* W3  = (const float*)d_in[10];
    const float* as3 = (const float*)d_in[11];
    const float* ad3 = (const float*)d_in[12];
    const float* b3  = (const float*)d_in[13];
    float* out = (float*)d_out;

    void* p;
    float *x, *asb, *adb;
    __half* hh;
    int *counts, *offs, *cursor, *esrc, *part;
    cudaGetSymbolAddress(&p, g_hh);     hh = (__half*)p;
    cudaGetSymbolAddress(&p, g_x);      x = (float*)p;
    cudaGetSymbolAddress(&p, g_as);     asb = (float*)p;
    cudaGetSymbolAddress(&p, g_ad);     adb = (float*)p;
    cudaGetSymbolAddress(&p, g_counts); counts = (int*)p;
    cudaGetSymbolAddress(&p, g_offs);   offs = (int*)p;
    cudaGetSymbolAddress(&p, g_cursor); cursor = (int*)p;
    cudaGetSymbolAddress(&p, g_esrc);   esrc = (int*)p;
    cudaGetSymbolAddress(&p, g_part);   part = (int*)p;

    const int NB = (NN + 1023) / 1024;  // 49

    // CSR by dst (counting sort), rebuilt every call (deterministic work)
    k_init<<<(NN + 255) / 256, 256>>>(counts);
    k_hist<<<(EE + 255) / 256, 256>>>(A, counts);
    k_scan1<<<NB, 1024>>>(counts, offs, part);
    k_scan3<<<NB, 1024>>>(offs, part, counts, cursor);
    k_scatter<<<(ETOT + 255) / 256, 256>>>(A, cursor, esrc);

    const int GB = (NN + 127) / 128;  // 391 blocks
    const int AB = (NN + 7) / 8;      // warp-per-node blocks

    // Layer 1
    gemm_tc<128><<<GB, 256>>>(X, W1, as1, ad1, hh, asb, adb);
    agg128_k<true><<<AB, 256>>>(hh, asb, adb, esrc, offs, b1, x);
    // Layer 2
    gemm_tc<128><<<GB, 256>>>(x, W2, as2, ad2, hh, asb, adb);
    agg128_k<true><<<AB, 256>>>(hh, asb, adb, esrc, offs, b2, x);
    // Layer 3 (mean over heads)
    gemm_tc<64><<<GB, 256>>>(x, W3, as3, ad3, hh, asb, adb);
    agg64_mean_k<<<AB, 256>>>(hh, asb, adb, esrc, offs, b3, out);
}